// round 1
// baseline (speedup 1.0000x reference)
#include <cuda_runtime.h>
#include <math.h>

// ---------------- constants ----------------
constexpr int   T       = 65536;
constexpr int   S       = 128;
constexpr int   H       = 256;
constexpr int   A       = 8;
constexpr float GAMMA_C = 0.99f;
constexpr float GL      = 0.99f * 0.95f;     // gamma * lambda
constexpr float EPSC    = 0.2f;
constexpr float LOG2PI  = 1.8378770664093453f;

// ---------------- device scratch (static: no allocations allowed) ----------------
__device__ float g_h1v[(size_t)T * H];
__device__ float g_h1p[(size_t)T * H];
__device__ float g_h2v[(size_t)T * H];
__device__ float g_h2p[(size_t)T * H];
__device__ float g_values[T];
__device__ float g_ratio[T];
__device__ float g_Aloc[T];
__device__ float g_Bloc[T];
__device__ float g_adv[T];
__device__ float g_Ablk[64];
__device__ float g_Bblk[64];
__device__ float g_Gin[64];
__device__ float g_vlast[1];
__device__ float g_stats[4];   // [0]=sum adv, [1]=sum adv^2, [2]=sum pg, [3]=sum vf

// ---------------- fused GEMM + bias + tanh:  Y[M,256] = tanh(X[M,K] @ W[K,256] + b) ----------------
// block tile 128x128, 256 threads, thread tile 8x8, K-slab 16
__global__ __launch_bounds__(256) void gemm_tanh(
    const float* __restrict__ X, const float* __restrict__ W,
    const float* __restrict__ bias, float* __restrict__ Y, int K)
{
    __shared__ float As[16][132];   // transposed slab, padded (132 % 4 == 0 keeps float4 align)
    __shared__ float Bs[16][128];

    const int m0  = blockIdx.x * 128;
    const int n0  = blockIdx.y * 128;
    const int tid = threadIdx.x;
    const int tr  = tid >> 4;        // 0..15
    const int tc  = tid & 15;        // 0..15

    float acc[8][8] = {};

    for (int k0 = 0; k0 < K; k0 += 16) {
        // A slab: 128 rows x 16 cols -> transposed into As[k][row]
        #pragma unroll
        for (int i = 0; i < 2; i++) {
            int f   = tid + i * 256;          // float4 index, 512 total
            int row = f >> 2;
            int c4  = f & 3;
            float4 v = *(const float4*)(X + (size_t)(m0 + row) * K + k0 + c4 * 4);
            As[c4 * 4 + 0][row] = v.x;
            As[c4 * 4 + 1][row] = v.y;
            As[c4 * 4 + 2][row] = v.z;
            As[c4 * 4 + 3][row] = v.w;
        }
        // B slab: 16 rows x 128 cols, natural layout
        #pragma unroll
        for (int i = 0; i < 2; i++) {
            int f   = tid + i * 256;
            int row = f >> 5;
            int c4  = f & 31;
            *(float4*)&Bs[row][c4 * 4] =
                *(const float4*)(W + (size_t)(k0 + row) * 256 + n0 + c4 * 4);
        }
        __syncthreads();

        #pragma unroll
        for (int k = 0; k < 16; k++) {
            float a[8], b[8];
            *(float4*)&a[0] = *(const float4*)&As[k][tr * 8];
            *(float4*)&a[4] = *(const float4*)&As[k][tr * 8 + 4];
            *(float4*)&b[0] = *(const float4*)&Bs[k][tc * 8];
            *(float4*)&b[4] = *(const float4*)&Bs[k][tc * 8 + 4];
            #pragma unroll
            for (int i = 0; i < 8; i++)
                #pragma unroll
                for (int j = 0; j < 8; j++)
                    acc[i][j] = fmaf(a[i], b[j], acc[i][j]);
        }
        __syncthreads();
    }

    float bj[8];
    #pragma unroll
    for (int j = 0; j < 8; j++) bj[j] = bias[n0 + tc * 8 + j];

    #pragma unroll
    for (int i = 0; i < 8; i++) {
        int row = m0 + tr * 8 + i;
        float o[8];
        #pragma unroll
        for (int j = 0; j < 8; j++) o[j] = tanhf(acc[i][j] + bj[j]);
        float* yp = Y + (size_t)row * 256 + n0 + tc * 8;
        *(float4*)&yp[0] = make_float4(o[0], o[1], o[2], o[3]);
        *(float4*)&yp[4] = make_float4(o[4], o[5], o[6], o[7]);
    }
}

// ---------------- value of the single bootstrap state sp[T-1] ----------------
__global__ __launch_bounds__(256) void vlast_kernel(
    const float* __restrict__ sp,
    const float* __restrict__ vW1, const float* __restrict__ vb1,
    const float* __restrict__ vW2, const float* __restrict__ vb2,
    const float* __restrict__ vhW, const float* __restrict__ vhb)
{
    __shared__ float x[S];
    __shared__ float h1[H];
    __shared__ float h2[H];
    __shared__ float red[8];
    int tid = threadIdx.x;
    if (tid < S) x[tid] = sp[(size_t)(T - 1) * S + tid];
    __syncthreads();

    float s = 0.f;
    for (int k = 0; k < S; k++) s = fmaf(x[k], vW1[(size_t)k * 256 + tid], s);
    h1[tid] = tanhf(s + vb1[tid]);
    __syncthreads();

    s = 0.f;
    for (int k = 0; k < H; k++) s = fmaf(h1[k], vW2[(size_t)k * 256 + tid], s);
    h2[tid] = tanhf(s + vb2[tid]);
    __syncthreads();

    float p = h2[tid] * vhW[tid];
    #pragma unroll
    for (int o = 16; o; o >>= 1) p += __shfl_down_sync(0xffffffffu, p, o);
    if ((tid & 31) == 0) red[tid >> 5] = p;
    __syncthreads();
    if (tid == 0) {
        float tot = 0.f;
        #pragma unroll
        for (int w = 0; w < 8; w++) tot += red[w];
        g_vlast[0] = tot + vhb[0];
    }
}

// ---------------- heads: values[t], ratio[t] (log_prob folded in) ----------------
__global__ __launch_bounds__(256) void heads_kernel(
    const float* __restrict__ vhW, const float* __restrict__ vhb,
    const float* __restrict__ muW, const float* __restrict__ mub,
    const float* __restrict__ logstd,
    const float* __restrict__ a, const float* __restrict__ lpo)
{
    __shared__ float s_vhW[H];
    __shared__ float s_muW[H * A];
    int tid = threadIdx.x;
    if (tid < H) s_vhW[tid] = vhW[tid];
    for (int i = tid; i < H * A; i += 256) s_muW[i] = muW[i];
    __syncthreads();

    int warp = tid >> 5, lane = tid & 31;
    int row  = blockIdx.x * 8 + warp;

    const float* hv = g_h2v + (size_t)row * H + lane * 8;
    const float* hp = g_h2p + (size_t)row * H + lane * 8;
    float4 v0 = *(const float4*)hv,       v1 = *(const float4*)(hv + 4);
    float4 p0 = *(const float4*)hp,       p1 = *(const float4*)(hp + 4);
    float hvv[8] = {v0.x, v0.y, v0.z, v0.w, v1.x, v1.y, v1.z, v1.w};
    float hpp[8] = {p0.x, p0.y, p0.z, p0.w, p1.x, p1.y, p1.z, p1.w};

    float sv = 0.f;
    float am[A] = {};
    #pragma unroll
    for (int kk = 0; kk < 8; kk++) {
        int k = lane * 8 + kk;
        sv = fmaf(hvv[kk], s_vhW[k], sv);
        #pragma unroll
        for (int j = 0; j < A; j++)
            am[j] = fmaf(hpp[kk], s_muW[k * A + j], am[j]);
    }
    #pragma unroll
    for (int o = 16; o; o >>= 1) {
        sv += __shfl_down_sync(0xffffffffu, sv, o);
        #pragma unroll
        for (int j = 0; j < A; j++)
            am[j] += __shfl_down_sync(0xffffffffu, am[j], o);
    }

    if (lane == 0) {
        g_values[row] = sv + vhb[0];
        float lp = 0.f;
        #pragma unroll
        for (int j = 0; j < A; j++) {
            float mu = am[j] + mub[j];
            float ls = logstd[j];
            float d  = (a[(size_t)row * A + j] - mu) * expf(-ls);
            lp += -0.5f * d * d - ls;
        }
        lp -= 0.5f * LOG2PI * (float)A;
        g_ratio[row] = expf(lp - lpo[row]);
    }
}

// ---------------- GAE parallel scan (reversed-index linear recurrence) ----------------
// u = T-1-t. g[u] = delta[u] + (gl*m[u]) * g[u-1]. Composite (a,b): g -> a*g + b.
__global__ __launch_bounds__(1024) void scan1(
    const float* __restrict__ r, const float* __restrict__ dmask)
{
    int u = blockIdx.x * 1024 + threadIdx.x;
    int t = T - 1 - u;
    float m  = dmask[t];
    float nv = (t == T - 1) ? g_vlast[0] : g_values[t + 1];
    float bb = r[t] + GAMMA_C * nv * m - g_values[t];   // delta
    float aa = GL * m;

    int lane = threadIdx.x & 31, warp = threadIdx.x >> 5;
    #pragma unroll
    for (int off = 1; off < 32; off <<= 1) {
        float ap = __shfl_up_sync(0xffffffffu, aa, off);
        float bp = __shfl_up_sync(0xffffffffu, bb, off);
        if (lane >= off) { bb = fmaf(aa, bp, bb); aa *= ap; }
    }
    __shared__ float wA[32], wB[32];
    if (lane == 31) { wA[warp] = aa; wB[warp] = bb; }
    __syncthreads();
    if (warp == 0) {
        float a2 = wA[lane], b2 = wB[lane];
        #pragma unroll
        for (int off = 1; off < 32; off <<= 1) {
            float ap = __shfl_up_sync(0xffffffffu, a2, off);
            float bp = __shfl_up_sync(0xffffffffu, b2, off);
            if (lane >= off) { b2 = fmaf(a2, bp, b2); a2 *= ap; }
        }
        wA[lane] = a2; wB[lane] = b2;
    }
    __syncthreads();
    if (warp > 0) {
        float pa = wA[warp - 1], pb = wB[warp - 1];
        bb = fmaf(aa, pb, bb);
        aa *= pa;
    }
    g_Aloc[u] = aa;
    g_Bloc[u] = bb;
    if (threadIdx.x == 1023) { g_Ablk[blockIdx.x] = aa; g_Bblk[blockIdx.x] = bb; }
}

__global__ void scan2()
{
    if (threadIdx.x == 0) {
        float g = 0.f;
        for (int j = 0; j < 64; j++) {
            g_Gin[j] = g;
            g = fmaf(g_Ablk[j], g, g_Bblk[j]);
        }
    }
    if (threadIdx.x < 4) g_stats[threadIdx.x] = 0.f;   // zero accumulators (per graph replay)
}

__global__ __launch_bounds__(1024) void scan3()
{
    int u = blockIdx.x * 1024 + threadIdx.x;
    float g = fmaf(g_Aloc[u], g_Gin[blockIdx.x], g_Bloc[u]);
    g_adv[T - 1 - u] = g;

    float s1 = g, s2 = g * g;
    #pragma unroll
    for (int o = 16; o; o >>= 1) {
        s1 += __shfl_down_sync(0xffffffffu, s1, o);
        s2 += __shfl_down_sync(0xffffffffu, s2, o);
    }
    __shared__ float rA[32], rB[32];
    int lane = threadIdx.x & 31, warp = threadIdx.x >> 5;
    if (lane == 0) { rA[warp] = s1; rB[warp] = s2; }
    __syncthreads();
    if (warp == 0) {
        float t1 = rA[lane], t2 = rB[lane];
        #pragma unroll
        for (int o = 16; o; o >>= 1) {
            t1 += __shfl_down_sync(0xffffffffu, t1, o);
            t2 += __shfl_down_sync(0xffffffffu, t2, o);
        }
        if (lane == 0) {
            atomicAdd(&g_stats[0], t1);
            atomicAdd(&g_stats[1], t2);
        }
    }
}

// ---------------- PPO loss terms. vf_loss = mean huber(adv_raw)  [diff = -adv_raw, huber even] ----------------
__global__ __launch_bounds__(256) void loss_kernel()
{
    int t = blockIdx.x * 256 + threadIdx.x;
    float mean = g_stats[0] * (1.f / (float)T);
    float var  = (g_stats[1] - (float)T * mean * mean) * (1.f / (float)(T - 1));
    float sd   = sqrtf(fmaxf(var, 0.f));

    float adv  = g_adv[t];
    float advn = (adv - mean) / (sd + 1e-8f);
    float rt   = g_ratio[t];
    float clip = fminf(fmaxf(rt, 1.f - EPSC), 1.f + EPSC);
    float pg   = -fminf(rt * advn, clip * advn);
    float ax   = fabsf(adv);
    float vf   = (ax < 1.f) ? 0.5f * adv * adv : ax - 0.5f;

    #pragma unroll
    for (int o = 16; o; o >>= 1) {
        pg += __shfl_down_sync(0xffffffffu, pg, o);
        vf += __shfl_down_sync(0xffffffffu, vf, o);
    }
    __shared__ float rA[8], rB[8];
    int lane = threadIdx.x & 31, warp = threadIdx.x >> 5;
    if (lane == 0) { rA[warp] = pg; rB[warp] = vf; }
    __syncthreads();
    if (warp == 0 && lane < 8) {
        float t1 = rA[lane], t2 = rB[lane];
        #pragma unroll
        for (int o = 4; o; o >>= 1) {
            t1 += __shfl_down_sync(0xffu, t1, o);
            t2 += __shfl_down_sync(0xffu, t2, o);
        }
        if (lane == 0) {
            atomicAdd(&g_stats[2], t1);
            atomicAdd(&g_stats[3], t2);
        }
    }
}

__global__ void finalize_kernel(const float* __restrict__ logstd, float* __restrict__ out)
{
    if (threadIdx.x == 0) {
        float ent = 0.f;
        #pragma unroll
        for (int j = 0; j < A; j++) ent += 0.5f + 0.5f * LOG2PI + logstd[j];
        ent *= (1.f / (float)A);
        out[0] = g_stats[2] * (1.f / (float)T)
               + 0.5f * g_stats[3] * (1.f / (float)T)
               - 0.01f * ent;
    }
}

// ---------------- launch ----------------
static float* sym_addr(const void* symbol)
{
    void* p = nullptr;
    cudaGetSymbolAddress(&p, symbol);
    return (float*)p;
}

extern "C" void kernel_launch(void* const* d_in, const int* in_sizes, int n_in,
                              void* d_out, int out_size)
{
    const float* s_in  = (const float*)d_in[0];
    const float* a_in  = (const float*)d_in[1];
    const float* r_in  = (const float*)d_in[2];
    const float* sp_in = (const float*)d_in[3];
    const float* lpo   = (const float*)d_in[4];
    const float* dmask = (const float*)d_in[5];
    const float* piW1  = (const float*)d_in[6];
    const float* pib1  = (const float*)d_in[7];
    const float* piW2  = (const float*)d_in[8];
    const float* pib2  = (const float*)d_in[9];
    const float* muW   = (const float*)d_in[10];
    const float* mub   = (const float*)d_in[11];
    const float* lstd  = (const float*)d_in[12];
    const float* vW1   = (const float*)d_in[13];
    const float* vb1   = (const float*)d_in[14];
    const float* vW2   = (const float*)d_in[15];
    const float* vb2   = (const float*)d_in[16];
    const float* vhW   = (const float*)d_in[17];
    const float* vhb   = (const float*)d_in[18];
    float* out = (float*)d_out;

    float* h1v = sym_addr(g_h1v);
    float* h1p = sym_addr(g_h1p);
    float* h2v = sym_addr(g_h2v);
    float* h2p = sym_addr(g_h2p);

    dim3 gg(T / 128, 2);

    // layer 1 (both nets), layer 2 (both nets)
    gemm_tanh<<<gg, 256>>>(s_in, vW1, vb1, h1v, S);
    gemm_tanh<<<gg, 256>>>(s_in, piW1, pib1, h1p, S);
    gemm_tanh<<<gg, 256>>>(h1v, vW2, vb2, h2v, H);
    gemm_tanh<<<gg, 256>>>(h1p, piW2, pib2, h2p, H);

    vlast_kernel<<<1, 256>>>(sp_in, vW1, vb1, vW2, vb2, vhW, vhb);
    heads_kernel<<<T / 8, 256>>>(vhW, vhb, muW, mub, lstd, a_in, lpo);

    scan1<<<64, 1024>>>(r_in, dmask);
    scan2<<<1, 32>>>();
    scan3<<<64, 1024>>>();

    loss_kernel<<<T / 256, 256>>>();
    finalize_kernel<<<1, 32>>>(lstd, out);
}

// round 2
// speedup vs baseline: 1.0012x; 1.0012x over previous
#include <cuda_runtime.h>
#include <math.h>

// ---------------- constants ----------------
constexpr int   T       = 65536;
constexpr int   S       = 128;
constexpr int   H       = 256;
constexpr int   A       = 8;
constexpr float GAMMA_C = 0.99f;
constexpr float GL      = 0.99f * 0.95f;     // gamma * lambda
constexpr float EPSC    = 0.2f;
constexpr float LOG2PI  = 1.8378770664093453f;

// ---------------- device scratch (static: no allocations allowed) ----------------
__device__ float g_h1v[(size_t)T * H];
__device__ float g_h1p[(size_t)T * H];
__device__ float g_h2v[(size_t)T * H];
__device__ float g_h2p[(size_t)T * H];
__device__ float g_values[T];
__device__ float g_ratio[T];
__device__ float g_Aloc[T];
__device__ float g_Bloc[T];
__device__ float g_adv[T];
__device__ float g_Ablk[64];
__device__ float g_Bblk[64];
__device__ float g_Gin[64];
__device__ float g_vlast[1];
__device__ float g_stats[4];   // [0]=sum adv, [1]=sum adv^2, [2]=sum pg, [3]=sum vf

// ---------------- fused GEMM + bias + tanh:  Y[M,256] = tanh(X[M,K] @ W[K,256] + b) ----------------
// block tile 128x128, 256 threads, thread tile 8x8, K-slab 16
__global__ __launch_bounds__(256) void gemm_tanh(
    const float* __restrict__ X, const float* __restrict__ W,
    const float* __restrict__ bias, float* __restrict__ Y, int K)
{
    __shared__ float As[16][132];   // transposed slab, padded (132 % 4 == 0 keeps float4 align)
    __shared__ float Bs[16][128];

    const int m0  = blockIdx.x * 128;
    const int n0  = blockIdx.y * 128;
    const int tid = threadIdx.x;
    const int tr  = tid >> 4;        // 0..15
    const int tc  = tid & 15;        // 0..15

    float acc[8][8] = {};

    for (int k0 = 0; k0 < K; k0 += 16) {
        // A slab: 128 rows x 16 cols -> transposed into As[k][row]
        #pragma unroll
        for (int i = 0; i < 2; i++) {
            int f   = tid + i * 256;          // float4 index, 512 total
            int row = f >> 2;
            int c4  = f & 3;
            float4 v = *(const float4*)(X + (size_t)(m0 + row) * K + k0 + c4 * 4);
            As[c4 * 4 + 0][row] = v.x;
            As[c4 * 4 + 1][row] = v.y;
            As[c4 * 4 + 2][row] = v.z;
            As[c4 * 4 + 3][row] = v.w;
        }
        // B slab: 16 rows x 128 cols, natural layout
        #pragma unroll
        for (int i = 0; i < 2; i++) {
            int f   = tid + i * 256;
            int row = f >> 5;
            int c4  = f & 31;
            *(float4*)&Bs[row][c4 * 4] =
                *(const float4*)(W + (size_t)(k0 + row) * 256 + n0 + c4 * 4);
        }
        __syncthreads();

        #pragma unroll
        for (int k = 0; k < 16; k++) {
            float a[8], b[8];
            *(float4*)&a[0] = *(const float4*)&As[k][tr * 8];
            *(float4*)&a[4] = *(const float4*)&As[k][tr * 8 + 4];
            *(float4*)&b[0] = *(const float4*)&Bs[k][tc * 8];
            *(float4*)&b[4] = *(const float4*)&Bs[k][tc * 8 + 4];
            #pragma unroll
            for (int i = 0; i < 8; i++)
                #pragma unroll
                for (int j = 0; j < 8; j++)
                    acc[i][j] = fmaf(a[i], b[j], acc[i][j]);
        }
        __syncthreads();
    }

    float bj[8];
    #pragma unroll
    for (int j = 0; j < 8; j++) bj[j] = bias[n0 + tc * 8 + j];

    #pragma unroll
    for (int i = 0; i < 8; i++) {
        int row = m0 + tr * 8 + i;
        float o[8];
        #pragma unroll
        for (int j = 0; j < 8; j++) o[j] = tanhf(acc[i][j] + bj[j]);
        float* yp = Y + (size_t)row * 256 + n0 + tc * 8;
        *(float4*)&yp[0] = make_float4(o[0], o[1], o[2], o[3]);
        *(float4*)&yp[4] = make_float4(o[4], o[5], o[6], o[7]);
    }
}

// ---------------- value of the single bootstrap state sp[T-1] ----------------
__global__ __launch_bounds__(256) void vlast_kernel(
    const float* __restrict__ sp,
    const float* __restrict__ vW1, const float* __restrict__ vb1,
    const float* __restrict__ vW2, const float* __restrict__ vb2,
    const float* __restrict__ vhW, const float* __restrict__ vhb)
{
    __shared__ float x[S];
    __shared__ float h1[H];
    __shared__ float h2[H];
    __shared__ float red[8];
    int tid = threadIdx.x;
    if (tid < S) x[tid] = sp[(size_t)(T - 1) * S + tid];
    __syncthreads();

    float s = 0.f;
    for (int k = 0; k < S; k++) s = fmaf(x[k], vW1[(size_t)k * 256 + tid], s);
    h1[tid] = tanhf(s + vb1[tid]);
    __syncthreads();

    s = 0.f;
    for (int k = 0; k < H; k++) s = fmaf(h1[k], vW2[(size_t)k * 256 + tid], s);
    h2[tid] = tanhf(s + vb2[tid]);
    __syncthreads();

    float p = h2[tid] * vhW[tid];
    #pragma unroll
    for (int o = 16; o; o >>= 1) p += __shfl_down_sync(0xffffffffu, p, o);
    if ((tid & 31) == 0) red[tid >> 5] = p;
    __syncthreads();
    if (tid == 0) {
        float tot = 0.f;
        #pragma unroll
        for (int w = 0; w < 8; w++) tot += red[w];
        g_vlast[0] = tot + vhb[0];
    }
}

// ---------------- heads: values[t], ratio[t] (log_prob folded in) ----------------
__global__ __launch_bounds__(256) void heads_kernel(
    const float* __restrict__ vhW, const float* __restrict__ vhb,
    const float* __restrict__ muW, const float* __restrict__ mub,
    const float* __restrict__ logstd,
    const float* __restrict__ a, const float* __restrict__ lpo)
{
    __shared__ float s_vhW[H];
    __shared__ float s_muW[H * A];
    int tid = threadIdx.x;
    if (tid < H) s_vhW[tid] = vhW[tid];
    for (int i = tid; i < H * A; i += 256) s_muW[i] = muW[i];
    __syncthreads();

    int warp = tid >> 5, lane = tid & 31;
    int row  = blockIdx.x * 8 + warp;

    const float* hv = g_h2v + (size_t)row * H + lane * 8;
    const float* hp = g_h2p + (size_t)row * H + lane * 8;
    float4 v0 = *(const float4*)hv,       v1 = *(const float4*)(hv + 4);
    float4 p0 = *(const float4*)hp,       p1 = *(const float4*)(hp + 4);
    float hvv[8] = {v0.x, v0.y, v0.z, v0.w, v1.x, v1.y, v1.z, v1.w};
    float hpp[8] = {p0.x, p0.y, p0.z, p0.w, p1.x, p1.y, p1.z, p1.w};

    float sv = 0.f;
    float am[A] = {};
    #pragma unroll
    for (int kk = 0; kk < 8; kk++) {
        int k = lane * 8 + kk;
        sv = fmaf(hvv[kk], s_vhW[k], sv);
        #pragma unroll
        for (int j = 0; j < A; j++)
            am[j] = fmaf(hpp[kk], s_muW[k * A + j], am[j]);
    }
    #pragma unroll
    for (int o = 16; o; o >>= 1) {
        sv += __shfl_down_sync(0xffffffffu, sv, o);
        #pragma unroll
        for (int j = 0; j < A; j++)
            am[j] += __shfl_down_sync(0xffffffffu, am[j], o);
    }

    if (lane == 0) {
        g_values[row] = sv + vhb[0];
        float lp = 0.f;
        #pragma unroll
        for (int j = 0; j < A; j++) {
            float mu = am[j] + mub[j];
            float ls = logstd[j];
            float d  = (a[(size_t)row * A + j] - mu) * expf(-ls);
            lp += -0.5f * d * d - ls;
        }
        lp -= 0.5f * LOG2PI * (float)A;
        g_ratio[row] = expf(lp - lpo[row]);
    }
}

// ---------------- GAE parallel scan (reversed-index linear recurrence) ----------------
// u = T-1-t. g[u] = delta[u] + (gl*m[u]) * g[u-1]. Composite (a,b): g -> a*g + b.
__global__ __launch_bounds__(1024) void scan1(
    const float* __restrict__ r, const float* __restrict__ dmask)
{
    int u = blockIdx.x * 1024 + threadIdx.x;
    int t = T - 1 - u;
    float m  = dmask[t];
    float nv = (t == T - 1) ? g_vlast[0] : g_values[t + 1];
    float bb = r[t] + GAMMA_C * nv * m - g_values[t];   // delta
    float aa = GL * m;

    int lane = threadIdx.x & 31, warp = threadIdx.x >> 5;
    #pragma unroll
    for (int off = 1; off < 32; off <<= 1) {
        float ap = __shfl_up_sync(0xffffffffu, aa, off);
        float bp = __shfl_up_sync(0xffffffffu, bb, off);
        if (lane >= off) { bb = fmaf(aa, bp, bb); aa *= ap; }
    }
    __shared__ float wA[32], wB[32];
    if (lane == 31) { wA[warp] = aa; wB[warp] = bb; }
    __syncthreads();
    if (warp == 0) {
        float a2 = wA[lane], b2 = wB[lane];
        #pragma unroll
        for (int off = 1; off < 32; off <<= 1) {
            float ap = __shfl_up_sync(0xffffffffu, a2, off);
            float bp = __shfl_up_sync(0xffffffffu, b2, off);
            if (lane >= off) { b2 = fmaf(a2, bp, b2); a2 *= ap; }
        }
        wA[lane] = a2; wB[lane] = b2;
    }
    __syncthreads();
    if (warp > 0) {
        float pa = wA[warp - 1], pb = wB[warp - 1];
        bb = fmaf(aa, pb, bb);
        aa *= pa;
    }
    g_Aloc[u] = aa;
    g_Bloc[u] = bb;
    if (threadIdx.x == 1023) { g_Ablk[blockIdx.x] = aa; g_Bblk[blockIdx.x] = bb; }
}

__global__ void scan2()
{
    if (threadIdx.x == 0) {
        float g = 0.f;
        for (int j = 0; j < 64; j++) {
            g_Gin[j] = g;
            g = fmaf(g_Ablk[j], g, g_Bblk[j]);
        }
    }
    if (threadIdx.x < 4) g_stats[threadIdx.x] = 0.f;   // zero accumulators (per graph replay)
}

__global__ __launch_bounds__(1024) void scan3()
{
    int u = blockIdx.x * 1024 + threadIdx.x;
    float g = fmaf(g_Aloc[u], g_Gin[blockIdx.x], g_Bloc[u]);
    g_adv[T - 1 - u] = g;

    float s1 = g, s2 = g * g;
    #pragma unroll
    for (int o = 16; o; o >>= 1) {
        s1 += __shfl_down_sync(0xffffffffu, s1, o);
        s2 += __shfl_down_sync(0xffffffffu, s2, o);
    }
    __shared__ float rA[32], rB[32];
    int lane = threadIdx.x & 31, warp = threadIdx.x >> 5;
    if (lane == 0) { rA[warp] = s1; rB[warp] = s2; }
    __syncthreads();
    if (warp == 0) {
        float t1 = rA[lane], t2 = rB[lane];
        #pragma unroll
        for (int o = 16; o; o >>= 1) {
            t1 += __shfl_down_sync(0xffffffffu, t1, o);
            t2 += __shfl_down_sync(0xffffffffu, t2, o);
        }
        if (lane == 0) {
            atomicAdd(&g_stats[0], t1);
            atomicAdd(&g_stats[1], t2);
        }
    }
}

// ---------------- PPO loss terms. vf_loss = mean huber(adv_raw)  [diff = -adv_raw, huber even] ----------------
__global__ __launch_bounds__(256) void loss_kernel()
{
    int t = blockIdx.x * 256 + threadIdx.x;
    float mean = g_stats[0] * (1.f / (float)T);
    float var  = (g_stats[1] - (float)T * mean * mean) * (1.f / (float)(T - 1));
    float sd   = sqrtf(fmaxf(var, 0.f));

    float adv  = g_adv[t];
    float advn = (adv - mean) / (sd + 1e-8f);
    float rt   = g_ratio[t];
    float clip = fminf(fmaxf(rt, 1.f - EPSC), 1.f + EPSC);
    float pg   = -fminf(rt * advn, clip * advn);
    float ax   = fabsf(adv);
    float vf   = (ax < 1.f) ? 0.5f * adv * adv : ax - 0.5f;

    #pragma unroll
    for (int o = 16; o; o >>= 1) {
        pg += __shfl_down_sync(0xffffffffu, pg, o);
        vf += __shfl_down_sync(0xffffffffu, vf, o);
    }
    __shared__ float rA[8], rB[8];
    int lane = threadIdx.x & 31, warp = threadIdx.x >> 5;
    if (lane == 0) { rA[warp] = pg; rB[warp] = vf; }
    __syncthreads();
    if (warp == 0 && lane < 8) {
        float t1 = rA[lane], t2 = rB[lane];
        #pragma unroll
        for (int o = 4; o; o >>= 1) {
            t1 += __shfl_down_sync(0xffu, t1, o);
            t2 += __shfl_down_sync(0xffu, t2, o);
        }
        if (lane == 0) {
            atomicAdd(&g_stats[2], t1);
            atomicAdd(&g_stats[3], t2);
        }
    }
}

__global__ void finalize_kernel(const float* __restrict__ logstd, float* __restrict__ out)
{
    if (threadIdx.x == 0) {
        float ent = 0.f;
        #pragma unroll
        for (int j = 0; j < A; j++) ent += 0.5f + 0.5f * LOG2PI + logstd[j];
        ent *= (1.f / (float)A);
        out[0] = g_stats[2] * (1.f / (float)T)
               + 0.5f * g_stats[3] * (1.f / (float)T)
               - 0.01f * ent;
    }
}

// ---------------- launch ----------------
static float* sym_addr(const void* symbol)
{
    void* p = nullptr;
    cudaGetSymbolAddress(&p, symbol);
    return (float*)p;
}

extern "C" void kernel_launch(void* const* d_in, const int* in_sizes, int n_in,
                              void* d_out, int out_size)
{
    const float* s_in  = (const float*)d_in[0];
    const float* a_in  = (const float*)d_in[1];
    const float* r_in  = (const float*)d_in[2];
    const float* sp_in = (const float*)d_in[3];
    const float* lpo   = (const float*)d_in[4];
    const float* dmask = (const float*)d_in[5];
    const float* piW1  = (const float*)d_in[6];
    const float* pib1  = (const float*)d_in[7];
    const float* piW2  = (const float*)d_in[8];
    const float* pib2  = (const float*)d_in[9];
    const float* muW   = (const float*)d_in[10];
    const float* mub   = (const float*)d_in[11];
    const float* lstd  = (const float*)d_in[12];
    const float* vW1   = (const float*)d_in[13];
    const float* vb1   = (const float*)d_in[14];
    const float* vW2   = (const float*)d_in[15];
    const float* vb2   = (const float*)d_in[16];
    const float* vhW   = (const float*)d_in[17];
    const float* vhb   = (const float*)d_in[18];
    float* out = (float*)d_out;

    float* h1v = sym_addr(g_h1v);
    float* h1p = sym_addr(g_h1p);
    float* h2v = sym_addr(g_h2v);
    float* h2p = sym_addr(g_h2p);

    dim3 gg(T / 128, 2);

    // layer 1 (both nets), layer 2 (both nets)
    gemm_tanh<<<gg, 256>>>(s_in, vW1, vb1, h1v, S);
    gemm_tanh<<<gg, 256>>>(s_in, piW1, pib1, h1p, S);
    gemm_tanh<<<gg, 256>>>(h1v, vW2, vb2, h2v, H);
    gemm_tanh<<<gg, 256>>>(h1p, piW2, pib2, h2p, H);

    vlast_kernel<<<1, 256>>>(sp_in, vW1, vb1, vW2, vb2, vhW, vhb);
    heads_kernel<<<T / 8, 256>>>(vhW, vhb, muW, mub, lstd, a_in, lpo);

    scan1<<<64, 1024>>>(r_in, dmask);
    scan2<<<1, 32>>>();
    scan3<<<64, 1024>>>();

    loss_kernel<<<T / 256, 256>>>();
    finalize_kernel<<<1, 32>>>(lstd, out);
}

// round 4
// speedup vs baseline: 1.2373x; 1.2359x over previous
#include <cuda_runtime.h>
#include <cuda_bf16.h>
#include <math.h>
#include <stdint.h>

// ---------------- constants ----------------
constexpr int   T       = 65536;
constexpr int   S       = 128;
constexpr int   H       = 256;
constexpr int   A       = 8;
constexpr float GAMMA_C = 0.99f;
constexpr float GL      = 0.99f * 0.95f;     // gamma * lambda
constexpr float EPSC    = 0.2f;
constexpr float LOG2PI  = 1.8378770664093453f;

// ---------------- device scratch (static: no allocations allowed) ----------------
__device__ __align__(16) __nv_bfloat16 g_s_h[(size_t)T * S];
__device__ __align__(16) __nv_bfloat16 g_s_l[(size_t)T * S];
__device__ __align__(16) __nv_bfloat16 g_h1v_h[(size_t)T * H], g_h1v_l[(size_t)T * H];
__device__ __align__(16) __nv_bfloat16 g_h1p_h[(size_t)T * H], g_h1p_l[(size_t)T * H];
__device__ __align__(16) float g_h2v[(size_t)T * H];
__device__ __align__(16) float g_h2p[(size_t)T * H];
__device__ float g_values[T];
__device__ float g_ratio[T];
__device__ float g_Aloc[T];
__device__ float g_Bloc[T];
__device__ float g_adv[T];
__device__ float g_Ablk[64];
__device__ float g_Bblk[64];
__device__ float g_Gin[64];
__device__ float g_vlast[1];
__device__ float g_stats[4];   // [0]=sum adv, [1]=sum adv^2, [2]=sum pg, [3]=sum vf

// transposed + split weights: [N=256][K] bf16, hi and lo parts
__device__ __align__(16) __nv_bfloat16 g_w1v_h[32768], g_w1v_l[32768];
__device__ __align__(16) __nv_bfloat16 g_w1p_h[32768], g_w1p_l[32768];
__device__ __align__(16) __nv_bfloat16 g_w2v_h[65536], g_w2v_l[65536];
__device__ __align__(16) __nv_bfloat16 g_w2p_h[65536], g_w2p_l[65536];

// ---------------- PTX helpers (sm_80-compatible: mma.sync / ldmatrix / cp.async) ----------------
__device__ __forceinline__ uint32_t smem_u32(const void* p) {
    return (uint32_t)__cvta_generic_to_shared(p);
}

__device__ __forceinline__ void cpasync16(uint32_t dst, const void* src) {
    asm volatile("cp.async.cg.shared.global [%0], [%1], 16;" :: "r"(dst), "l"(src));
}

#define CP_COMMIT()  asm volatile("cp.async.commit_group;")
#define CP_WAIT0()   asm volatile("cp.async.wait_group 0;" ::: "memory")

#define LDSM4(r0, r1, r2, r3, addr)                                                 \
    asm volatile("ldmatrix.sync.aligned.m8n8.x4.shared.b16 {%0,%1,%2,%3}, [%4];"    \
        : "=r"(r0), "=r"(r1), "=r"(r2), "=r"(r3) : "r"(addr))

#define MMA16816(cc, a, b0, b1)                                                     \
    asm volatile("mma.sync.aligned.m16n8k16.row.col.f32.bf16.bf16.f32 "             \
        "{%0,%1,%2,%3}, {%4,%5,%6,%7}, {%8,%9}, {%0,%1,%2,%3};"                     \
        : "+f"((cc)[0]), "+f"((cc)[1]), "+f"((cc)[2]), "+f"((cc)[3])                \
        : "r"((a)[0]), "r"((a)[1]), "r"((a)[2]), "r"((a)[3]), "r"(b0), "r"(b1))

// ---------------- weight split + transpose: W[K,256] fp32 -> Wt[256,K] bf16 hi/lo ----------------
__global__ void split_tr(const float* __restrict__ W1v, const float* __restrict__ W1p,
                         const float* __restrict__ W2v, const float* __restrict__ W2p)
{
    int idx = blockIdx.x * 256 + threadIdx.x;    // 0 .. 196607
    const float* W; __nv_bfloat16 *Hh, *Ll; int K, base;
    if (idx < 32768)       { W = W1v; Hh = g_w1v_h; Ll = g_w1v_l; K = 128; base = 0; }
    else if (idx < 65536)  { W = W1p; Hh = g_w1p_h; Ll = g_w1p_l; K = 128; base = 32768; }
    else if (idx < 131072) { W = W2v; Hh = g_w2v_h; Ll = g_w2v_l; K = 256; base = 65536; }
    else                   { W = W2p; Hh = g_w2p_h; Ll = g_w2p_l; K = 256; base = 131072; }
    int j = idx - base;
    int k = j >> 8, n = j & 255;                 // W row-major [K][256], coalesced read
    float x = W[j];
    __nv_bfloat16 h = __float2bfloat16(x);
    Hh[(size_t)n * K + k] = h;
    Ll[(size_t)n * K + k] = __float2bfloat16(x - __bfloat162float(h));
}

// ---------------- input split: X fp32 -> bf16 hi/lo ----------------
__global__ void split_input(const float* __restrict__ X,
                            __nv_bfloat16* __restrict__ Xh, __nv_bfloat16* __restrict__ Xl)
{
    int i = blockIdx.x * 256 + threadIdx.x;      // each handles 4 floats
    float4 v = ((const float4*)X)[i];
    __nv_bfloat162 h0, h1, l0, l1;
    h0.x = __float2bfloat16(v.x); l0.x = __float2bfloat16(v.x - __bfloat162float(h0.x));
    h0.y = __float2bfloat16(v.y); l0.y = __float2bfloat16(v.y - __bfloat162float(h0.y));
    h1.x = __float2bfloat16(v.z); l1.x = __float2bfloat16(v.z - __bfloat162float(h1.x));
    h1.y = __float2bfloat16(v.w); l1.y = __float2bfloat16(v.w - __bfloat162float(h1.y));
    ((__nv_bfloat162*)Xh)[2 * i]     = h0;
    ((__nv_bfloat162*)Xh)[2 * i + 1] = h1;
    ((__nv_bfloat162*)Xl)[2 * i]     = l0;
    ((__nv_bfloat162*)Xl)[2 * i + 1] = l1;
}

// ---------------- tensor-core GEMM (mma.sync bf16, split-bf16 3-term = ~fp32) ----------------
// Y[T,256] = tanh(X[T,K] @ W[K,256] + b)
// A given pre-split as bf16 hi/lo [T][K]; B pre-split [256][K].
// mode 0: write fp32 Y. mode 1: write bf16 hi/lo split (feeds next layer).
#define SMEM_SZ (131072 + 512)

__global__ void __launch_bounds__(256, 1) gemm_mma(
    const uint4* __restrict__ Ahi, const uint4* __restrict__ Alo,
    const __nv_bfloat16* __restrict__ Bhp, const __nv_bfloat16* __restrict__ Blp,
    const float* __restrict__ bias,
    float* __restrict__ Yf,
    __nv_bfloat16* __restrict__ Yh, __nv_bfloat16* __restrict__ Yl,
    int K, int mode)
{
    extern __shared__ char smem[];
    const int KG = K >> 3;                 // 16B groups per row
    const uint32_t sAh_u = smem_u32(smem);
    const uint32_t sAl_u = sAh_u + 32768;
    const uint32_t sBh_u = sAh_u + 65536;
    const uint32_t sBl_u = sAh_u + 98304;
    float* bias_s = (float*)(smem + 131072);

    const int tid = threadIdx.x;
    const int wid = tid >> 5, lane = tid & 31;
    const int m0 = blockIdx.x * 128;
    const int n0 = blockIdx.y * 128;
    const int mbase = (wid >> 2) * 64;     // warp m within block (2 warps)
    const int nbase = (wid & 3) * 32;      // warp n within block (4 warps)

    if (tid < 128) bias_s[tid] = bias[n0 + tid];

    float c[4][4][4] = {};

    const int l7    = lane & 7;
    const int rowA  = mbase + (lane & 15);
    const int halfA = lane >> 4;                       // kg +0/+1
    const int rowB  = (lane & 7) + ((lane >> 4) & 1) * 8;
    const int halfB = (lane >> 3) & 1;

    const int nchunks = K >> 7;
    for (int ch = 0; ch < nchunks; ch++) {
        const int kg0 = ch * 16;

        // ---- load chunk: 4 tiles x 128 rows x 16 groups, swizzled, via cp.async ----
        #pragma unroll
        for (int i = 0; i < 8; i++) {
            int idx = i * 256 + tid;
            int row = idx >> 4, g = idx & 15;
            uint32_t dst = (uint32_t)(row * 256 + ((((g & 7) ^ (row & 7)) | (g & 8)) << 4));
            size_t srcA = (size_t)(m0 + row) * KG + kg0 + g;
            size_t srcB = (size_t)(n0 + row) * KG + kg0 + g;
            cpasync16(sAh_u + dst, Ahi + srcA);
            cpasync16(sAl_u + dst, Alo + srcA);
            cpasync16(sBh_u + dst, (const uint4*)Bhp + srcB);
            cpasync16(sBl_u + dst, (const uint4*)Blp + srcB);
        }
        CP_COMMIT();
        CP_WAIT0();
        __syncthreads();

        // ---- 8 k16 steps ----
        #pragma unroll
        for (int ks = 0; ks < 8; ks++) {
            int kgA = 2 * ks + halfA;
            uint32_t pgA = (uint32_t)((((kgA & 7) ^ l7) | (kgA & 8)) << 4);
            int kgB = 2 * ks + halfB;
            uint32_t pgB = (uint32_t)((((kgB & 7) ^ l7) | (kgB & 8)) << 4);

            uint32_t ah[4][4], al[4][4];
            #pragma unroll
            for (int mi = 0; mi < 4; mi++) {
                uint32_t ro = (uint32_t)((rowA + 16 * mi) * 256) + pgA;
                LDSM4(ah[mi][0], ah[mi][1], ah[mi][2], ah[mi][3], sAh_u + ro);
                LDSM4(al[mi][0], al[mi][1], al[mi][2], al[mi][3], sAl_u + ro);
            }
            uint32_t bh[2][4], bl[2][4];
            #pragma unroll
            for (int p = 0; p < 2; p++) {
                uint32_t ro = (uint32_t)((nbase + p * 16 + rowB) * 256) + pgB;
                LDSM4(bh[p][0], bh[p][1], bh[p][2], bh[p][3], sBh_u + ro);
                LDSM4(bl[p][0], bl[p][1], bl[p][2], bl[p][3], sBl_u + ro);
            }
            #pragma unroll
            for (int mi = 0; mi < 4; mi++)
                #pragma unroll
                for (int p = 0; p < 2; p++)
                    #pragma unroll
                    for (int s2 = 0; s2 < 2; s2++) {
                        float* cc = c[mi][p * 2 + s2];
                        MMA16816(cc, ah[mi], bh[p][2 * s2], bh[p][2 * s2 + 1]);
                        MMA16816(cc, ah[mi], bl[p][2 * s2], bl[p][2 * s2 + 1]);
                        MMA16816(cc, al[mi], bh[p][2 * s2], bh[p][2 * s2 + 1]);
                    }
        }
        __syncthreads();
    }

    // ---- epilogue: bias + tanh, store ----
    const int g = lane >> 2, t = lane & 3;
    #pragma unroll
    for (int mi = 0; mi < 4; mi++) {
        int row = m0 + mbase + mi * 16 + g;
        #pragma unroll
        for (int ni = 0; ni < 4; ni++) {
            int colb = nbase + ni * 8 + 2 * t;
            int col  = n0 + colb;
            float b0 = bias_s[colb], b1 = bias_s[colb + 1];
            float v0 = tanhf(c[mi][ni][0] + b0);
            float v1 = tanhf(c[mi][ni][1] + b1);
            float v2 = tanhf(c[mi][ni][2] + b0);
            float v3 = tanhf(c[mi][ni][3] + b1);
            if (mode == 0) {
                *(float2*)(Yf + (size_t)row * 256 + col)       = make_float2(v0, v1);
                *(float2*)(Yf + (size_t)(row + 8) * 256 + col) = make_float2(v2, v3);
            } else {
                __nv_bfloat162 hA, lA, hB, lB;
                hA.x = __float2bfloat16(v0); lA.x = __float2bfloat16(v0 - __bfloat162float(hA.x));
                hA.y = __float2bfloat16(v1); lA.y = __float2bfloat16(v1 - __bfloat162float(hA.y));
                hB.x = __float2bfloat16(v2); lB.x = __float2bfloat16(v2 - __bfloat162float(hB.x));
                hB.y = __float2bfloat16(v3); lB.y = __float2bfloat16(v3 - __bfloat162float(hB.y));
                *(__nv_bfloat162*)(Yh + (size_t)row * 256 + col)       = hA;
                *(__nv_bfloat162*)(Yl + (size_t)row * 256 + col)       = lA;
                *(__nv_bfloat162*)(Yh + (size_t)(row + 8) * 256 + col) = hB;
                *(__nv_bfloat162*)(Yl + (size_t)(row + 8) * 256 + col) = lB;
            }
        }
    }
}

// ---------------- value of the single bootstrap state sp[T-1] ----------------
__global__ __launch_bounds__(256) void vlast_kernel(
    const float* __restrict__ sp,
    const float* __restrict__ vW1, const float* __restrict__ vb1,
    const float* __restrict__ vW2, const float* __restrict__ vb2,
    const float* __restrict__ vhW, const float* __restrict__ vhb)
{
    __shared__ float x[S];
    __shared__ float h1[H];
    __shared__ float h2[H];
    __shared__ float red[8];
    int tid = threadIdx.x;
    if (tid < S) x[tid] = sp[(size_t)(T - 1) * S + tid];
    __syncthreads();

    float s = 0.f;
    for (int k = 0; k < S; k++) s = fmaf(x[k], vW1[(size_t)k * 256 + tid], s);
    h1[tid] = tanhf(s + vb1[tid]);
    __syncthreads();

    s = 0.f;
    for (int k = 0; k < H; k++) s = fmaf(h1[k], vW2[(size_t)k * 256 + tid], s);
    h2[tid] = tanhf(s + vb2[tid]);
    __syncthreads();

    float p = h2[tid] * vhW[tid];
    #pragma unroll
    for (int o = 16; o; o >>= 1) p += __shfl_down_sync(0xffffffffu, p, o);
    if ((tid & 31) == 0) red[tid >> 5] = p;
    __syncthreads();
    if (tid == 0) {
        float tot = 0.f;
        #pragma unroll
        for (int w = 0; w < 8; w++) tot += red[w];
        g_vlast[0] = tot + vhb[0];
    }
}

// ---------------- heads: values[t], ratio[t] (log_prob folded in) ----------------
__global__ __launch_bounds__(256) void heads_kernel(
    const float* __restrict__ vhW, const float* __restrict__ vhb,
    const float* __restrict__ muW, const float* __restrict__ mub,
    const float* __restrict__ logstd,
    const float* __restrict__ a, const float* __restrict__ lpo)
{
    __shared__ float s_vhW[H];
    __shared__ float s_muW[H * A];
    int tid = threadIdx.x;
    if (tid < H) s_vhW[tid] = vhW[tid];
    for (int i = tid; i < H * A; i += 256) s_muW[i] = muW[i];
    __syncthreads();

    int warp = tid >> 5, lane = tid & 31;
    int row  = blockIdx.x * 8 + warp;

    const float* hv = g_h2v + (size_t)row * H + lane * 8;
    const float* hp = g_h2p + (size_t)row * H + lane * 8;
    float4 v0 = *(const float4*)hv,       v1 = *(const float4*)(hv + 4);
    float4 p0 = *(const float4*)hp,       p1 = *(const float4*)(hp + 4);
    float hvv[8] = {v0.x, v0.y, v0.z, v0.w, v1.x, v1.y, v1.z, v1.w};
    float hpp[8] = {p0.x, p0.y, p0.z, p0.w, p1.x, p1.y, p1.z, p1.w};

    float sv = 0.f;
    float am[A] = {};
    #pragma unroll
    for (int kk = 0; kk < 8; kk++) {
        int k = lane * 8 + kk;
        sv = fmaf(hvv[kk], s_vhW[k], sv);
        #pragma unroll
        for (int j = 0; j < A; j++)
            am[j] = fmaf(hpp[kk], s_muW[k * A + j], am[j]);
    }
    #pragma unroll
    for (int o = 16; o; o >>= 1) {
        sv += __shfl_down_sync(0xffffffffu, sv, o);
        #pragma unroll
        for (int j = 0; j < A; j++)
            am[j] += __shfl_down_sync(0xffffffffu, am[j], o);
    }

    if (lane == 0) {
        g_values[row] = sv + vhb[0];
        float lp = 0.f;
        #pragma unroll
        for (int j = 0; j < A; j++) {
            float mu = am[j] + mub[j];
            float ls = logstd[j];
            float d  = (a[(size_t)row * A + j] - mu) * expf(-ls);
            lp += -0.5f * d * d - ls;
        }
        lp -= 0.5f * LOG2PI * (float)A;
        g_ratio[row] = expf(lp - lpo[row]);
    }
}

// ---------------- GAE parallel scan (reversed-index linear recurrence) ----------------
__global__ __launch_bounds__(1024) void scan1(
    const float* __restrict__ r, const float* __restrict__ dmask)
{
    int u = blockIdx.x * 1024 + threadIdx.x;
    int t = T - 1 - u;
    float m  = dmask[t];
    float nv = (t == T - 1) ? g_vlast[0] : g_values[t + 1];
    float bb = r[t] + GAMMA_C * nv * m - g_values[t];   // delta
    float aa = GL * m;

    int lane = threadIdx.x & 31, warp = threadIdx.x >> 5;
    #pragma unroll
    for (int off = 1; off < 32; off <<= 1) {
        float ap = __shfl_up_sync(0xffffffffu, aa, off);
        float bp = __shfl_up_sync(0xffffffffu, bb, off);
        if (lane >= off) { bb = fmaf(aa, bp, bb); aa *= ap; }
    }
    __shared__ float wA[32], wB[32];
    if (lane == 31) { wA[warp] = aa; wB[warp] = bb; }
    __syncthreads();
    if (warp == 0) {
        float a2 = wA[lane], b2 = wB[lane];
        #pragma unroll
        for (int off = 1; off < 32; off <<= 1) {
            float ap = __shfl_up_sync(0xffffffffu, a2, off);
            float bp = __shfl_up_sync(0xffffffffu, b2, off);
            if (lane >= off) { b2 = fmaf(a2, bp, b2); a2 *= ap; }
        }
        wA[lane] = a2; wB[lane] = b2;
    }
    __syncthreads();
    if (warp > 0) {
        float pa = wA[warp - 1], pb = wB[warp - 1];
        bb = fmaf(aa, pb, bb);
        aa *= pa;
    }
    g_Aloc[u] = aa;
    g_Bloc[u] = bb;
    if (threadIdx.x == 1023) { g_Ablk[blockIdx.x] = aa; g_Bblk[blockIdx.x] = bb; }
}

__global__ void scan2()
{
    if (threadIdx.x == 0) {
        float g = 0.f;
        for (int j = 0; j < 64; j++) {
            g_Gin[j] = g;
            g = fmaf(g_Ablk[j], g, g_Bblk[j]);
        }
    }
    if (threadIdx.x < 4) g_stats[threadIdx.x] = 0.f;   // zero accumulators (per graph replay)
}

__global__ __launch_bounds__(1024) void scan3()
{
    int u = blockIdx.x * 1024 + threadIdx.x;
    float g = fmaf(g_Aloc[u], g_Gin[blockIdx.x], g_Bloc[u]);
    g_adv[T - 1 - u] = g;

    float s1 = g, s2 = g * g;
    #pragma unroll
    for (int o = 16; o; o >>= 1) {
        s1 += __shfl_down_sync(0xffffffffu, s1, o);
        s2 += __shfl_down_sync(0xffffffffu, s2, o);
    }
    __shared__ float rA[32], rB[32];
    int lane = threadIdx.x & 31, warp = threadIdx.x >> 5;
    if (lane == 0) { rA[warp] = s1; rB[warp] = s2; }
    __syncthreads();
    if (warp == 0) {
        float t1 = rA[lane], t2 = rB[lane];
        #pragma unroll
        for (int o = 16; o; o >>= 1) {
            t1 += __shfl_down_sync(0xffffffffu, t1, o);
            t2 += __shfl_down_sync(0xffffffffu, t2, o);
        }
        if (lane == 0) {
            atomicAdd(&g_stats[0], t1);
            atomicAdd(&g_stats[1], t2);
        }
    }
}

// ---------------- PPO loss terms. vf_loss = mean huber(adv_raw)  [diff = -adv_raw, huber even] ----------------
__global__ __launch_bounds__(256) void loss_kernel()
{
    int t = blockIdx.x * 256 + threadIdx.x;
    float mean = g_stats[0] * (1.f / (float)T);
    float var  = (g_stats[1] - (float)T * mean * mean) * (1.f / (float)(T - 1));
    float sd   = sqrtf(fmaxf(var, 0.f));

    float adv  = g_adv[t];
    float advn = (adv - mean) / (sd + 1e-8f);
    float rt   = g_ratio[t];
    float clip = fminf(fmaxf(rt, 1.f - EPSC), 1.f + EPSC);
    float pg   = -fminf(rt * advn, clip * advn);
    float ax   = fabsf(adv);
    float vf   = (ax < 1.f) ? 0.5f * adv * adv : ax - 0.5f;

    #pragma unroll
    for (int o = 16; o; o >>= 1) {
        pg += __shfl_down_sync(0xffffffffu, pg, o);
        vf += __shfl_down_sync(0xffffffffu, vf, o);
    }
    __shared__ float rA[8], rB[8];
    int lane = threadIdx.x & 31, warp = threadIdx.x >> 5;
    if (lane == 0) { rA[warp] = pg; rB[warp] = vf; }
    __syncthreads();
    if (warp == 0 && lane < 8) {
        float t1 = rA[lane], t2 = rB[lane];
        #pragma unroll
        for (int o = 4; o; o >>= 1) {
            t1 += __shfl_down_sync(0xffu, t1, o);
            t2 += __shfl_down_sync(0xffu, t2, o);
        }
        if (lane == 0) {
            atomicAdd(&g_stats[2], t1);
            atomicAdd(&g_stats[3], t2);
        }
    }
}

__global__ void finalize_kernel(const float* __restrict__ logstd, float* __restrict__ out)
{
    if (threadIdx.x == 0) {
        float ent = 0.f;
        #pragma unroll
        for (int j = 0; j < A; j++) ent += 0.5f + 0.5f * LOG2PI + logstd[j];
        ent *= (1.f / (float)A);
        out[0] = g_stats[2] * (1.f / (float)T)
               + 0.5f * g_stats[3] * (1.f / (float)T)
               - 0.01f * ent;
    }
}

// ---------------- launch ----------------
static void* sym_addr(const void* symbol)
{
    void* p = nullptr;
    cudaGetSymbolAddress(&p, symbol);
    return p;
}

extern "C" void kernel_launch(void* const* d_in, const int* in_sizes, int n_in,
                              void* d_out, int out_size)
{
    const float* s_in  = (const float*)d_in[0];
    const float* a_in  = (const float*)d_in[1];
    const float* r_in  = (const float*)d_in[2];
    const float* sp_in = (const float*)d_in[3];
    const float* lpo   = (const float*)d_in[4];
    const float* dmask = (const float*)d_in[5];
    const float* piW1  = (const float*)d_in[6];
    const float* pib1  = (const float*)d_in[7];
    const float* piW2  = (const float*)d_in[8];
    const float* pib2  = (const float*)d_in[9];
    const float* muW   = (const float*)d_in[10];
    const float* mub   = (const float*)d_in[11];
    const float* lstd  = (const float*)d_in[12];
    const float* vW1   = (const float*)d_in[13];
    const float* vb1   = (const float*)d_in[14];
    const float* vW2   = (const float*)d_in[15];
    const float* vb2   = (const float*)d_in[16];
    const float* vhW   = (const float*)d_in[17];
    const float* vhb   = (const float*)d_in[18];
    float* out = (float*)d_out;

    __nv_bfloat16* s_h  = (__nv_bfloat16*)sym_addr(g_s_h);
    __nv_bfloat16* s_l  = (__nv_bfloat16*)sym_addr(g_s_l);
    __nv_bfloat16* h1vh = (__nv_bfloat16*)sym_addr(g_h1v_h);
    __nv_bfloat16* h1vl = (__nv_bfloat16*)sym_addr(g_h1v_l);
    __nv_bfloat16* h1ph = (__nv_bfloat16*)sym_addr(g_h1p_h);
    __nv_bfloat16* h1pl = (__nv_bfloat16*)sym_addr(g_h1p_l);
    float* h2v = (float*)sym_addr(g_h2v);
    float* h2p = (float*)sym_addr(g_h2p);

    __nv_bfloat16* w1vh = (__nv_bfloat16*)sym_addr(g_w1v_h);
    __nv_bfloat16* w1vl = (__nv_bfloat16*)sym_addr(g_w1v_l);
    __nv_bfloat16* w1ph = (__nv_bfloat16*)sym_addr(g_w1p_h);
    __nv_bfloat16* w1pl = (__nv_bfloat16*)sym_addr(g_w1p_l);
    __nv_bfloat16* w2vh = (__nv_bfloat16*)sym_addr(g_w2v_h);
    __nv_bfloat16* w2vl = (__nv_bfloat16*)sym_addr(g_w2v_l);
    __nv_bfloat16* w2ph = (__nv_bfloat16*)sym_addr(g_w2p_h);
    __nv_bfloat16* w2pl = (__nv_bfloat16*)sym_addr(g_w2p_l);

    cudaFuncSetAttribute(gemm_mma, cudaFuncAttributeMaxDynamicSharedMemorySize, SMEM_SZ);

    // prep: weight split/transpose + input split (tiny)
    split_tr<<<768, 256>>>(vW1, piW1, vW2, piW2);
    split_input<<<(T * S / 4) / 256, 256>>>(s_in, s_h, s_l);

    // bootstrap value (independent of big GEMMs)
    vlast_kernel<<<1, 256>>>(sp_in, vW1, vb1, vW2, vb2, vhW, vhb);

    dim3 gg(T / 128, 2);
    // layer 1 (both nets): write split bf16 h1
    gemm_mma<<<gg, 256, SMEM_SZ>>>((const uint4*)s_h, (const uint4*)s_l, w1vh, w1vl,
                                   vb1, nullptr, h1vh, h1vl, 128, 1);
    gemm_mma<<<gg, 256, SMEM_SZ>>>((const uint4*)s_h, (const uint4*)s_l, w1ph, w1pl,
                                   pib1, nullptr, h1ph, h1pl, 128, 1);
    // layer 2 (both nets): write fp32 h2
    gemm_mma<<<gg, 256, SMEM_SZ>>>((const uint4*)h1vh, (const uint4*)h1vl, w2vh, w2vl,
                                   vb2, h2v, nullptr, nullptr, 256, 0);
    gemm_mma<<<gg, 256, SMEM_SZ>>>((const uint4*)h1ph, (const uint4*)h1pl, w2ph, w2pl,
                                   pib2, h2p, nullptr, nullptr, 256, 0);

    heads_kernel<<<T / 8, 256>>>(vhW, vhb, muW, mub, lstd, a_in, lpo);

    scan1<<<64, 1024>>>(r_in, dmask);
    scan2<<<1, 32>>>();
    scan3<<<64, 1024>>>();

    loss_kernel<<<T / 256, 256>>>();
    finalize_kernel<<<1, 32>>>(lstd, out);
}

// round 5
// speedup vs baseline: 2.2743x; 1.8381x over previous
#include <cuda_runtime.h>
#include <cuda_bf16.h>
#include <math.h>
#include <stdint.h>

// ---------------- constants ----------------
constexpr int   T       = 65536;
constexpr int   S       = 128;
constexpr int   H       = 256;
constexpr int   A       = 8;
constexpr float GAMMA_C = 0.99f;
constexpr float GL      = 0.99f * 0.95f;     // gamma * lambda
constexpr float EPSC    = 0.2f;
constexpr float LOG2PI  = 1.8378770664093453f;

// ---------------- device scratch (static: no allocations allowed) ----------------
__device__ __align__(16) __nv_bfloat16 g_s_h[(size_t)T * S];
__device__ __align__(16) __nv_bfloat16 g_s_l[(size_t)T * S];
__device__ __align__(16) __nv_bfloat16 g_h1v_h[(size_t)T * H], g_h1v_l[(size_t)T * H];
__device__ __align__(16) __nv_bfloat16 g_h1p_h[(size_t)T * H], g_h1p_l[(size_t)T * H];
__device__ float g_values[T];
__device__ __align__(16) float g_mu[(size_t)T * A];
__device__ float g_Aloc[T];
__device__ float g_Bloc[T];
__device__ float g_adv[T];
__device__ float g_Ablk[64];
__device__ float g_Bblk[64];
__device__ float g_Gin[64];
__device__ float g_vlast[1];
__device__ float g_stats[4];   // [0]=sum adv, [1]=sum adv^2, [2]=sum pg, [3]=sum vf

// transposed + split weights: [N=256][K] bf16, hi and lo parts
__device__ __align__(16) __nv_bfloat16 g_w1v_h[32768], g_w1v_l[32768];
__device__ __align__(16) __nv_bfloat16 g_w1p_h[32768], g_w1p_l[32768];
__device__ __align__(16) __nv_bfloat16 g_w2v_h[65536], g_w2v_l[65536];
__device__ __align__(16) __nv_bfloat16 g_w2p_h[65536], g_w2p_l[65536];

// ---------------- PTX helpers ----------------
__device__ __forceinline__ uint32_t smem_u32(const void* p) {
    return (uint32_t)__cvta_generic_to_shared(p);
}

__device__ __forceinline__ void cpasync16(uint32_t dst, const void* src) {
    asm volatile("cp.async.cg.shared.global [%0], [%1], 16;" :: "r"(dst), "l"(src));
}

#define CP_COMMIT()  asm volatile("cp.async.commit_group;")
#define CP_WAIT0()   asm volatile("cp.async.wait_group 0;" ::: "memory")
#define CP_WAIT1()   asm volatile("cp.async.wait_group 1;" ::: "memory")

#define LDSM4(r0, r1, r2, r3, addr)                                                 \
    asm volatile("ldmatrix.sync.aligned.m8n8.x4.shared.b16 {%0,%1,%2,%3}, [%4];"    \
        : "=r"(r0), "=r"(r1), "=r"(r2), "=r"(r3) : "r"(addr))

#define MMA16816(cc, a, b0, b1)                                                     \
    asm volatile("mma.sync.aligned.m16n8k16.row.col.f32.bf16.bf16.f32 "             \
        "{%0,%1,%2,%3}, {%4,%5,%6,%7}, {%8,%9}, {%0,%1,%2,%3};"                     \
        : "+f"((cc)[0]), "+f"((cc)[1]), "+f"((cc)[2]), "+f"((cc)[3])                \
        : "r"((a)[0]), "r"((a)[1]), "r"((a)[2]), "r"((a)[3]), "r"(b0), "r"(b1))

// ---------------- weight split + transpose: W[K,256] fp32 -> Wt[256,K] bf16 hi/lo ----------------
__global__ void split_tr(const float* __restrict__ W1v, const float* __restrict__ W1p,
                         const float* __restrict__ W2v, const float* __restrict__ W2p)
{
    int idx = blockIdx.x * 256 + threadIdx.x;    // 0 .. 196607
    const float* W; __nv_bfloat16 *Hh, *Ll; int K, base;
    if (idx < 32768)       { W = W1v; Hh = g_w1v_h; Ll = g_w1v_l; K = 128; base = 0; }
    else if (idx < 65536)  { W = W1p; Hh = g_w1p_h; Ll = g_w1p_l; K = 128; base = 32768; }
    else if (idx < 131072) { W = W2v; Hh = g_w2v_h; Ll = g_w2v_l; K = 256; base = 65536; }
    else                   { W = W2p; Hh = g_w2p_h; Ll = g_w2p_l; K = 256; base = 131072; }
    int j = idx - base;
    int k = j >> 8, n = j & 255;                 // W row-major [K][256], coalesced read
    float x = W[j];
    __nv_bfloat16 h = __float2bfloat16(x);
    Hh[(size_t)n * K + k] = h;
    Ll[(size_t)n * K + k] = __float2bfloat16(x - __bfloat162float(h));
}

// ---------------- input split: X fp32 -> bf16 hi/lo ----------------
__global__ void split_input(const float* __restrict__ X,
                            __nv_bfloat16* __restrict__ Xh, __nv_bfloat16* __restrict__ Xl)
{
    int i = blockIdx.x * 256 + threadIdx.x;      // each handles 4 floats
    float4 v = ((const float4*)X)[i];
    __nv_bfloat162 h0, h1, l0, l1;
    h0.x = __float2bfloat16(v.x); l0.x = __float2bfloat16(v.x - __bfloat162float(h0.x));
    h0.y = __float2bfloat16(v.y); l0.y = __float2bfloat16(v.y - __bfloat162float(h0.y));
    h1.x = __float2bfloat16(v.z); l1.x = __float2bfloat16(v.z - __bfloat162float(h1.x));
    h1.y = __float2bfloat16(v.w); l1.y = __float2bfloat16(v.w - __bfloat162float(h1.y));
    ((__nv_bfloat162*)Xh)[2 * i]     = h0;
    ((__nv_bfloat162*)Xh)[2 * i + 1] = h1;
    ((__nv_bfloat162*)Xl)[2 * i]     = l0;
    ((__nv_bfloat162*)Xl)[2 * i + 1] = l1;
}

// ---------------- preset head accumulators ----------------
__global__ void presetK(const float* __restrict__ vhb, const float* __restrict__ mub)
{
    int t = blockIdx.x * 256 + threadIdx.x;
    g_values[t] = vhb[0];
    float4 m0 = *(const float4*)mub;
    float4 m1 = *(const float4*)(mub + 4);
    ((float4*)g_mu)[2 * t]     = m0;
    ((float4*)g_mu)[2 * t + 1] = m1;
}

// ---------------- pipelined tensor-core GEMM (mma.sync bf16, split-bf16 3-term) ----------------
// Y[T,256] = tanh(X[T,K] @ W[K,256] + b)
// block tile 128x128, grid (2 n-tiles, T/128 m-tiles). 2-stage cp.async pipeline, k-chunk 64.
// mode 1: write split bf16 Y (h1). mode 2: value head -> atomicAdd g_values.
// mode 3: mu head -> atomicAdd g_mu.
#define SMEM_SZ (131072 + 512 + 4096)

__global__ void __launch_bounds__(256, 1) gemm_f(
    const uint4* __restrict__ Ahi, const uint4* __restrict__ Alo,
    const uint4* __restrict__ Bhi, const uint4* __restrict__ Blo,
    const float* __restrict__ bias, int K, int mode,
    __nv_bfloat16* __restrict__ Yh, __nv_bfloat16* __restrict__ Yl,
    const float* __restrict__ headW, float* __restrict__ headOut)
{
    extern __shared__ char smem[];
    const uint32_t s0 = smem_u32(smem);            // stages at +0, +65536
    float* bias_s = (float*)(smem + 131072);
    float* hW_s   = (float*)(smem + 131072 + 512);

    const int tid = threadIdx.x;
    const int wid = tid >> 5, lane = tid & 31;
    const int n0 = blockIdx.x * 128;               // n-tile fast dim -> A dedupe in L2
    const int m0 = blockIdx.y * 128;
    const int mbase = (wid >> 2) * 64;
    const int nbase = (wid & 3) * 32;
    const int KG = K >> 3;                          // 16B groups per full row

    if (tid < 128) bias_s[tid] = bias[n0 + tid];
    if (mode == 2 && tid < 128) hW_s[tid] = headW[n0 + tid];
    if (mode == 3) {
        for (int i = tid; i < 1024; i += 256) hW_s[i] = headW[n0 * 8 + i];
    }

    float c[4][4][4] = {};

    const int l7    = lane & 7;
    const int rowA  = mbase + (lane & 15);
    const int halfA = lane >> 4;
    const int rowB  = (lane & 7) + ((lane >> 4) & 1) * 8;
    const int halfB = (lane >> 3) & 1;

    const int nc = K >> 6;                          // 64-wide chunks

    auto load_chunk = [&](int st, int ch) {
        uint32_t base = s0 + (uint32_t)st * 65536u;
        int kg0 = ch * 8;
        #pragma unroll
        for (int i = 0; i < 4; i++) {
            int idx = i * 256 + tid;
            int row = idx >> 3, g = idx & 7;
            uint32_t d = base + (uint32_t)(row * 128 + ((g ^ (row & 7)) << 4));
            size_t sA = (size_t)(m0 + row) * KG + kg0 + g;
            size_t sB = (size_t)(n0 + row) * KG + kg0 + g;
            cpasync16(d,          Ahi + sA);
            cpasync16(d + 16384,  Alo + sA);
            cpasync16(d + 32768,  Bhi + sB);
            cpasync16(d + 49152,  Blo + sB);
        }
    };

    load_chunk(0, 0); CP_COMMIT();

    for (int ch = 0; ch < nc; ch++) {
        if (ch + 1 < nc) { load_chunk((ch + 1) & 1, ch + 1); CP_COMMIT(); CP_WAIT1(); }
        else             { CP_WAIT0(); }
        __syncthreads();

        uint32_t base = s0 + (uint32_t)(ch & 1) * 65536u;
        #pragma unroll
        for (int ks = 0; ks < 4; ks++) {
            int kgA = 2 * ks + halfA;
            uint32_t pgA = (uint32_t)(((kgA ^ l7)) << 4);
            int kgB = 2 * ks + halfB;
            uint32_t pgB = (uint32_t)(((kgB ^ l7)) << 4);

            uint32_t ah[4][4], al[4][4];
            #pragma unroll
            for (int mi = 0; mi < 4; mi++) {
                uint32_t ro = base + (uint32_t)((rowA + 16 * mi) * 128) + pgA;
                LDSM4(ah[mi][0], ah[mi][1], ah[mi][2], ah[mi][3], ro);
                LDSM4(al[mi][0], al[mi][1], al[mi][2], al[mi][3], ro + 16384);
            }
            uint32_t bh[2][4], bl[2][4];
            #pragma unroll
            for (int p = 0; p < 2; p++) {
                uint32_t ro = base + (uint32_t)((nbase + p * 16 + rowB) * 128) + pgB;
                LDSM4(bh[p][0], bh[p][1], bh[p][2], bh[p][3], ro + 32768);
                LDSM4(bl[p][0], bl[p][1], bl[p][2], bl[p][3], ro + 49152);
            }
            #pragma unroll
            for (int mi = 0; mi < 4; mi++)
                #pragma unroll
                for (int p = 0; p < 2; p++)
                    #pragma unroll
                    for (int s2 = 0; s2 < 2; s2++) {
                        float* cc = c[mi][p * 2 + s2];
                        MMA16816(cc, ah[mi], bh[p][2 * s2], bh[p][2 * s2 + 1]);
                        MMA16816(cc, ah[mi], bl[p][2 * s2], bl[p][2 * s2 + 1]);
                        MMA16816(cc, al[mi], bh[p][2 * s2], bh[p][2 * s2 + 1]);
                    }
        }
        __syncthreads();
    }

    // ---- epilogue ----
    const int g = lane >> 2, tq = lane & 3;
    if (mode == 1) {
        #pragma unroll
        for (int mi = 0; mi < 4; mi++) {
            int row = m0 + mbase + mi * 16 + g;
            #pragma unroll
            for (int ni = 0; ni < 4; ni++) {
                int colb = nbase + ni * 8 + 2 * tq;
                int col  = n0 + colb;
                float b0 = bias_s[colb], b1 = bias_s[colb + 1];
                float v0 = tanhf(c[mi][ni][0] + b0);
                float v1 = tanhf(c[mi][ni][1] + b1);
                float v2 = tanhf(c[mi][ni][2] + b0);
                float v3 = tanhf(c[mi][ni][3] + b1);
                __nv_bfloat162 hA, lA, hB, lB;
                hA.x = __float2bfloat16(v0); lA.x = __float2bfloat16(v0 - __bfloat162float(hA.x));
                hA.y = __float2bfloat16(v1); lA.y = __float2bfloat16(v1 - __bfloat162float(hA.y));
                hB.x = __float2bfloat16(v2); lB.x = __float2bfloat16(v2 - __bfloat162float(hB.x));
                hB.y = __float2bfloat16(v3); lB.y = __float2bfloat16(v3 - __bfloat162float(hB.y));
                *(__nv_bfloat162*)(Yh + (size_t)row * 256 + col)       = hA;
                *(__nv_bfloat162*)(Yl + (size_t)row * 256 + col)       = lA;
                *(__nv_bfloat162*)(Yh + (size_t)(row + 8) * 256 + col) = hB;
                *(__nv_bfloat162*)(Yl + (size_t)(row + 8) * 256 + col) = lB;
            }
        }
    } else if (mode == 2) {
        #pragma unroll
        for (int mi = 0; mi < 4; mi++) {
            float pv0 = 0.f, pv1 = 0.f;
            #pragma unroll
            for (int ni = 0; ni < 4; ni++) {
                int colb = nbase + ni * 8 + 2 * tq;
                float b0 = bias_s[colb], b1 = bias_s[colb + 1];
                float w0 = hW_s[colb],   w1 = hW_s[colb + 1];
                pv0 += tanhf(c[mi][ni][0] + b0) * w0 + tanhf(c[mi][ni][1] + b1) * w1;
                pv1 += tanhf(c[mi][ni][2] + b0) * w0 + tanhf(c[mi][ni][3] + b1) * w1;
            }
            pv0 += __shfl_xor_sync(0xffffffffu, pv0, 1);
            pv0 += __shfl_xor_sync(0xffffffffu, pv0, 2);
            pv1 += __shfl_xor_sync(0xffffffffu, pv1, 1);
            pv1 += __shfl_xor_sync(0xffffffffu, pv1, 2);
            if (tq == 0) {
                int row = m0 + mbase + mi * 16 + g;
                atomicAdd(&headOut[row],     pv0);
                atomicAdd(&headOut[row + 8], pv1);
            }
        }
    } else {  // mode 3: mu head
        #pragma unroll
        for (int mi = 0; mi < 4; mi++) {
            float pm0[8] = {}, pm1[8] = {};
            #pragma unroll
            for (int ni = 0; ni < 4; ni++) {
                int colb = nbase + ni * 8 + 2 * tq;
                float b0 = bias_s[colb], b1 = bias_s[colb + 1];
                float t0 = tanhf(c[mi][ni][0] + b0);
                float t1 = tanhf(c[mi][ni][1] + b1);
                float t2 = tanhf(c[mi][ni][2] + b0);
                float t3 = tanhf(c[mi][ni][3] + b1);
                #pragma unroll
                for (int j = 0; j < 8; j++) {
                    float w0 = hW_s[colb * 8 + j], w1 = hW_s[(colb + 1) * 8 + j];
                    pm0[j] += t0 * w0 + t1 * w1;
                    pm1[j] += t2 * w0 + t3 * w1;
                }
            }
            #pragma unroll
            for (int j = 0; j < 8; j++) {
                pm0[j] += __shfl_xor_sync(0xffffffffu, pm0[j], 1);
                pm0[j] += __shfl_xor_sync(0xffffffffu, pm0[j], 2);
                pm1[j] += __shfl_xor_sync(0xffffffffu, pm1[j], 1);
                pm1[j] += __shfl_xor_sync(0xffffffffu, pm1[j], 2);
            }
            if (tq == 0) {
                int row = m0 + mbase + mi * 16 + g;
                #pragma unroll
                for (int j = 0; j < 8; j++) {
                    atomicAdd(&headOut[(size_t)row * 8 + j],       pm0[j]);
                    atomicAdd(&headOut[(size_t)(row + 8) * 8 + j], pm1[j]);
                }
            }
        }
    }
}

// ---------------- value of the single bootstrap state sp[T-1] ----------------
__global__ __launch_bounds__(256) void vlast_kernel(
    const float* __restrict__ sp,
    const float* __restrict__ vW1, const float* __restrict__ vb1,
    const float* __restrict__ vW2, const float* __restrict__ vb2,
    const float* __restrict__ vhW, const float* __restrict__ vhb)
{
    __shared__ float x[S];
    __shared__ float h1[H];
    __shared__ float h2[H];
    __shared__ float red[8];
    int tid = threadIdx.x;
    if (tid < S) x[tid] = sp[(size_t)(T - 1) * S + tid];
    __syncthreads();

    float s = 0.f;
    for (int k = 0; k < S; k++) s = fmaf(x[k], vW1[(size_t)k * 256 + tid], s);
    h1[tid] = tanhf(s + vb1[tid]);
    __syncthreads();

    s = 0.f;
    for (int k = 0; k < H; k++) s = fmaf(h1[k], vW2[(size_t)k * 256 + tid], s);
    h2[tid] = tanhf(s + vb2[tid]);
    __syncthreads();

    float p = h2[tid] * vhW[tid];
    #pragma unroll
    for (int o = 16; o; o >>= 1) p += __shfl_down_sync(0xffffffffu, p, o);
    if ((tid & 31) == 0) red[tid >> 5] = p;
    __syncthreads();
    if (tid == 0) {
        float tot = 0.f;
        #pragma unroll
        for (int w = 0; w < 8; w++) tot += red[w];
        g_vlast[0] = tot + vhb[0];
    }
}

// ---------------- GAE parallel scan (reversed-index linear recurrence) ----------------
__global__ __launch_bounds__(1024) void scan1(
    const float* __restrict__ r, const float* __restrict__ dmask)
{
    int u = blockIdx.x * 1024 + threadIdx.x;
    int t = T - 1 - u;
    float m  = dmask[t];
    float nv = (t == T - 1) ? g_vlast[0] : g_values[t + 1];
    float bb = r[t] + GAMMA_C * nv * m - g_values[t];   // delta
    float aa = GL * m;

    int lane = threadIdx.x & 31, warp = threadIdx.x >> 5;
    #pragma unroll
    for (int off = 1; off < 32; off <<= 1) {
        float ap = __shfl_up_sync(0xffffffffu, aa, off);
        float bp = __shfl_up_sync(0xffffffffu, bb, off);
        if (lane >= off) { bb = fmaf(aa, bp, bb); aa *= ap; }
    }
    __shared__ float wA[32], wB[32];
    if (lane == 31) { wA[warp] = aa; wB[warp] = bb; }
    __syncthreads();
    if (warp == 0) {
        float a2 = wA[lane], b2 = wB[lane];
        #pragma unroll
        for (int off = 1; off < 32; off <<= 1) {
            float ap = __shfl_up_sync(0xffffffffu, a2, off);
            float bp = __shfl_up_sync(0xffffffffu, b2, off);
            if (lane >= off) { b2 = fmaf(a2, bp, b2); a2 *= ap; }
        }
        wA[lane] = a2; wB[lane] = b2;
    }
    __syncthreads();
    if (warp > 0) {
        float pa = wA[warp - 1], pb = wB[warp - 1];
        bb = fmaf(aa, pb, bb);
        aa *= pa;
    }
    g_Aloc[u] = aa;
    g_Bloc[u] = bb;
    if (threadIdx.x == 1023) { g_Ablk[blockIdx.x] = aa; g_Bblk[blockIdx.x] = bb; }
}

__global__ void scan2()
{
    if (threadIdx.x == 0) {
        float g = 0.f;
        for (int j = 0; j < 64; j++) {
            g_Gin[j] = g;
            g = fmaf(g_Ablk[j], g, g_Bblk[j]);
        }
    }
    if (threadIdx.x < 4) g_stats[threadIdx.x] = 0.f;   // zero accumulators (per graph replay)
}

__global__ __launch_bounds__(1024) void scan3()
{
    int u = blockIdx.x * 1024 + threadIdx.x;
    float g = fmaf(g_Aloc[u], g_Gin[blockIdx.x], g_Bloc[u]);
    g_adv[T - 1 - u] = g;

    float s1 = g, s2 = g * g;
    #pragma unroll
    for (int o = 16; o; o >>= 1) {
        s1 += __shfl_down_sync(0xffffffffu, s1, o);
        s2 += __shfl_down_sync(0xffffffffu, s2, o);
    }
    __shared__ float rA[32], rB[32];
    int lane = threadIdx.x & 31, warp = threadIdx.x >> 5;
    if (lane == 0) { rA[warp] = s1; rB[warp] = s2; }
    __syncthreads();
    if (warp == 0) {
        float t1 = rA[lane], t2 = rB[lane];
        #pragma unroll
        for (int o = 16; o; o >>= 1) {
            t1 += __shfl_down_sync(0xffffffffu, t1, o);
            t2 += __shfl_down_sync(0xffffffffu, t2, o);
        }
        if (lane == 0) {
            atomicAdd(&g_stats[0], t1);
            atomicAdd(&g_stats[1], t2);
        }
    }
}

// ---------------- PPO loss terms (ratio computed inline from g_mu) ----------------
__global__ __launch_bounds__(256) void loss_kernel(
    const float* __restrict__ a, const float* __restrict__ lpo,
    const float* __restrict__ logstd)
{
    int t = blockIdx.x * 256 + threadIdx.x;
    float mean = g_stats[0] * (1.f / (float)T);
    float var  = (g_stats[1] - (float)T * mean * mean) * (1.f / (float)(T - 1));
    float sd   = sqrtf(fmaxf(var, 0.f));

    float lp = 0.f;
    #pragma unroll
    for (int j = 0; j < A; j++) {
        float mu = g_mu[(size_t)t * 8 + j];
        float ls = logstd[j];
        float d  = (a[(size_t)t * 8 + j] - mu) * expf(-ls);
        lp += -0.5f * d * d - ls;
    }
    lp -= 0.5f * LOG2PI * (float)A;
    float rt = expf(lp - lpo[t]);

    float adv  = g_adv[t];
    float advn = (adv - mean) / (sd + 1e-8f);
    float clip = fminf(fmaxf(rt, 1.f - EPSC), 1.f + EPSC);
    float pg   = -fminf(rt * advn, clip * advn);
    float ax   = fabsf(adv);
    float vf   = (ax < 1.f) ? 0.5f * adv * adv : ax - 0.5f;

    #pragma unroll
    for (int o = 16; o; o >>= 1) {
        pg += __shfl_down_sync(0xffffffffu, pg, o);
        vf += __shfl_down_sync(0xffffffffu, vf, o);
    }
    __shared__ float rA[8], rB[8];
    int lane = threadIdx.x & 31, warp = threadIdx.x >> 5;
    if (lane == 0) { rA[warp] = pg; rB[warp] = vf; }
    __syncthreads();
    if (warp == 0 && lane < 8) {
        float t1 = rA[lane], t2 = rB[lane];
        #pragma unroll
        for (int o = 4; o; o >>= 1) {
            t1 += __shfl_down_sync(0xffu, t1, o);
            t2 += __shfl_down_sync(0xffu, t2, o);
        }
        if (lane == 0) {
            atomicAdd(&g_stats[2], t1);
            atomicAdd(&g_stats[3], t2);
        }
    }
}

__global__ void finalize_kernel(const float* __restrict__ logstd, float* __restrict__ out)
{
    if (threadIdx.x == 0) {
        float ent = 0.f;
        #pragma unroll
        for (int j = 0; j < A; j++) ent += 0.5f + 0.5f * LOG2PI + logstd[j];
        ent *= (1.f / (float)A);
        out[0] = g_stats[2] * (1.f / (float)T)
               + 0.5f * g_stats[3] * (1.f / (float)T)
               - 0.01f * ent;
    }
}

// ---------------- launch ----------------
static void* sym_addr(const void* symbol)
{
    void* p = nullptr;
    cudaGetSymbolAddress(&p, symbol);
    return p;
}

extern "C" void kernel_launch(void* const* d_in, const int* in_sizes, int n_in,
                              void* d_out, int out_size)
{
    const float* s_in  = (const float*)d_in[0];
    const float* a_in  = (const float*)d_in[1];
    const float* r_in  = (const float*)d_in[2];
    const float* sp_in = (const float*)d_in[3];
    const float* lpo   = (const float*)d_in[4];
    const float* dmask = (const float*)d_in[5];
    const float* piW1  = (const float*)d_in[6];
    const float* pib1  = (const float*)d_in[7];
    const float* piW2  = (const float*)d_in[8];
    const float* pib2  = (const float*)d_in[9];
    const float* muW   = (const float*)d_in[10];
    const float* mub   = (const float*)d_in[11];
    const float* lstd  = (const float*)d_in[12];
    const float* vW1   = (const float*)d_in[13];
    const float* vb1   = (const float*)d_in[14];
    const float* vW2   = (const float*)d_in[15];
    const float* vb2   = (const float*)d_in[16];
    const float* vhW   = (const float*)d_in[17];
    const float* vhb   = (const float*)d_in[18];
    float* out = (float*)d_out;

    __nv_bfloat16* s_h  = (__nv_bfloat16*)sym_addr(g_s_h);
    __nv_bfloat16* s_l  = (__nv_bfloat16*)sym_addr(g_s_l);
    __nv_bfloat16* h1vh = (__nv_bfloat16*)sym_addr(g_h1v_h);
    __nv_bfloat16* h1vl = (__nv_bfloat16*)sym_addr(g_h1v_l);
    __nv_bfloat16* h1ph = (__nv_bfloat16*)sym_addr(g_h1p_h);
    __nv_bfloat16* h1pl = (__nv_bfloat16*)sym_addr(g_h1p_l);
    float* valp = (float*)sym_addr(g_values);
    float* mup  = (float*)sym_addr(g_mu);

    __nv_bfloat16* w1vh = (__nv_bfloat16*)sym_addr(g_w1v_h);
    __nv_bfloat16* w1vl = (__nv_bfloat16*)sym_addr(g_w1v_l);
    __nv_bfloat16* w1ph = (__nv_bfloat16*)sym_addr(g_w1p_h);
    __nv_bfloat16* w1pl = (__nv_bfloat16*)sym_addr(g_w1p_l);
    __nv_bfloat16* w2vh = (__nv_bfloat16*)sym_addr(g_w2v_h);
    __nv_bfloat16* w2vl = (__nv_bfloat16*)sym_addr(g_w2v_l);
    __nv_bfloat16* w2ph = (__nv_bfloat16*)sym_addr(g_w2p_h);
    __nv_bfloat16* w2pl = (__nv_bfloat16*)sym_addr(g_w2p_l);

    cudaFuncSetAttribute(gemm_f, cudaFuncAttributeMaxDynamicSharedMemorySize, SMEM_SZ);

    // prep (tiny)
    split_tr<<<768, 256>>>(vW1, piW1, vW2, piW2);
    split_input<<<(T * S / 4) / 256, 256>>>(s_in, s_h, s_l);
    presetK<<<T / 256, 256>>>(vhb, mub);
    vlast_kernel<<<1, 256>>>(sp_in, vW1, vb1, vW2, vb2, vhW, vhb);

    dim3 gg(2, T / 128);   // n-tile fast dim -> shared A tiles in same wave (L2 dedupe)
    // layer 1 (both nets): write split bf16 h1
    gemm_f<<<gg, 256, SMEM_SZ>>>((const uint4*)s_h, (const uint4*)s_l,
                                 (const uint4*)w1vh, (const uint4*)w1vl,
                                 vb1, 128, 1, h1vh, h1vl, nullptr, nullptr);
    gemm_f<<<gg, 256, SMEM_SZ>>>((const uint4*)s_h, (const uint4*)s_l,
                                 (const uint4*)w1ph, (const uint4*)w1pl,
                                 pib1, 128, 1, h1ph, h1pl, nullptr, nullptr);
    // layer 2 + fused heads (h2 never touches DRAM)
    gemm_f<<<gg, 256, SMEM_SZ>>>((const uint4*)h1vh, (const uint4*)h1vl,
                                 (const uint4*)w2vh, (const uint4*)w2vl,
                                 vb2, 256, 2, nullptr, nullptr, vhW, valp);
    gemm_f<<<gg, 256, SMEM_SZ>>>((const uint4*)h1ph, (const uint4*)h1pl,
                                 (const uint4*)w2ph, (const uint4*)w2pl,
                                 pib2, 256, 3, nullptr, nullptr, muW, mup);

    scan1<<<64, 1024>>>(r_in, dmask);
    scan2<<<1, 32>>>();
    scan3<<<64, 1024>>>();

    loss_kernel<<<T / 256, 256>>>(a_in, lpo, lstd);
    finalize_kernel<<<1, 32>>>(lstd, out);
}

// round 6
// speedup vs baseline: 2.3397x; 1.0287x over previous
#include <cuda_runtime.h>
#include <cuda_bf16.h>
#include <math.h>
#include <stdint.h>

// ---------------- constants ----------------
constexpr int   T       = 65536;
constexpr int   S       = 128;
constexpr int   H       = 256;
constexpr int   A       = 8;
constexpr float GAMMA_C = 0.99f;
constexpr float GL      = 0.99f * 0.95f;     // gamma * lambda
constexpr float EPSC    = 0.2f;
constexpr float LOG2PI  = 1.8378770664093453f;
constexpr int   TX      = T + 128;           // T plus bootstrap tile

// ---------------- device scratch (static: no allocations allowed) ----------------
__device__ __align__(16) __nv_bfloat16 g_s_h[(size_t)TX * S];
__device__ __align__(16) __nv_bfloat16 g_s_l[(size_t)TX * S];
__device__ __align__(16) __nv_bfloat16 g_h1v_h[(size_t)TX * H], g_h1v_l[(size_t)TX * H];
__device__ __align__(16) __nv_bfloat16 g_h1p_h[(size_t)TX * H], g_h1p_l[(size_t)TX * H];
__device__ float g_values[TX];               // [T] = bootstrap value v(sp[-1])
__device__ __align__(16) float g_mu[(size_t)T * A];
__device__ float g_Aloc[T];
__device__ float g_Bloc[T];
__device__ float g_adv[T];
__device__ float g_Ablk[64];
__device__ float g_Bblk[64];
__device__ float g_Gin[64];
__device__ float g_stats[4];   // [0]=sum adv, [1]=sum adv^2, [2]=sum pg, [3]=sum vf

// weights: layer1 combined [512][128] (rows 0-255 v, 256-511 p); layer2 [256][256] each
__device__ __align__(16) __nv_bfloat16 g_w1_h[65536], g_w1_l[65536];
__device__ __align__(16) __nv_bfloat16 g_w2v_h[65536], g_w2v_l[65536];
__device__ __align__(16) __nv_bfloat16 g_w2p_h[65536], g_w2p_l[65536];

// ---------------- PTX helpers ----------------
__device__ __forceinline__ uint32_t smem_u32(const void* p) {
    return (uint32_t)__cvta_generic_to_shared(p);
}

__device__ __forceinline__ void cpasync16(uint32_t dst, const void* src) {
    asm volatile("cp.async.cg.shared.global [%0], [%1], 16;" :: "r"(dst), "l"(src));
}

#define CP_COMMIT()  asm volatile("cp.async.commit_group;")
#define CP_WAIT0()   asm volatile("cp.async.wait_group 0;" ::: "memory")
#define CP_WAIT1()   asm volatile("cp.async.wait_group 1;" ::: "memory")

#define LDSM4(r0, r1, r2, r3, addr)                                                 \
    asm volatile("ldmatrix.sync.aligned.m8n8.x4.shared.b16 {%0,%1,%2,%3}, [%4];"    \
        : "=r"(r0), "=r"(r1), "=r"(r2), "=r"(r3) : "r"(addr))

#define MMA16816(cc, a, b0, b1)                                                     \
    asm volatile("mma.sync.aligned.m16n8k16.row.col.f32.bf16.bf16.f32 "             \
        "{%0,%1,%2,%3}, {%4,%5,%6,%7}, {%8,%9}, {%0,%1,%2,%3};"                     \
        : "+f"((cc)[0]), "+f"((cc)[1]), "+f"((cc)[2]), "+f"((cc)[3])                \
        : "r"((a)[0]), "r"((a)[1]), "r"((a)[2]), "r"((a)[3]), "r"(b0), "r"(b1))

// ---------------- shared GEMM mainloop (2-stage cp.async pipeline, k-chunk 64) ----------------
// A, B pointers pre-offset to tile origin. KG = 16B-groups per row. nc = K/64 chunks.
__device__ __forceinline__ void mma_tile(
    const uint4* __restrict__ Ahi, const uint4* __restrict__ Alo,
    const uint4* __restrict__ Bhi, const uint4* __restrict__ Blo,
    int KG, int nc, uint32_t s0, float c[4][4][4])
{
    const int tid = threadIdx.x;
    const int wid = tid >> 5, lane = tid & 31;
    const int mbase = (wid >> 2) * 64;
    const int nbase = (wid & 3) * 32;
    const int l7    = lane & 7;
    const int rowA  = mbase + (lane & 15);
    const int halfA = lane >> 4;
    const int rowB  = (lane & 7) + ((lane >> 4) & 1) * 8;
    const int halfB = (lane >> 3) & 1;

    auto load_chunk = [&](int st, int ch) {
        uint32_t base = s0 + (uint32_t)st * 65536u;
        int kg0 = ch * 8;
        #pragma unroll
        for (int i = 0; i < 4; i++) {
            int idx = i * 256 + tid;
            int row = idx >> 3, g = idx & 7;
            uint32_t d = base + (uint32_t)(row * 128 + ((g ^ (row & 7)) << 4));
            size_t sA = (size_t)row * KG + kg0 + g;
            size_t sB = (size_t)row * KG + kg0 + g;
            cpasync16(d,          Ahi + sA);
            cpasync16(d + 16384,  Alo + sA);
            cpasync16(d + 32768,  Bhi + sB);
            cpasync16(d + 49152,  Blo + sB);
        }
    };

    load_chunk(0, 0); CP_COMMIT();

    for (int ch = 0; ch < nc; ch++) {
        if (ch + 1 < nc) { load_chunk((ch + 1) & 1, ch + 1); CP_COMMIT(); CP_WAIT1(); }
        else             { CP_WAIT0(); }
        __syncthreads();

        uint32_t base = s0 + (uint32_t)(ch & 1) * 65536u;
        #pragma unroll
        for (int ks = 0; ks < 4; ks++) {
            int kgA = 2 * ks + halfA;
            uint32_t pgA = (uint32_t)((kgA ^ l7) << 4);
            int kgB = 2 * ks + halfB;
            uint32_t pgB = (uint32_t)((kgB ^ l7) << 4);

            uint32_t ah[4][4], al[4][4];
            #pragma unroll
            for (int mi = 0; mi < 4; mi++) {
                uint32_t ro = base + (uint32_t)((rowA + 16 * mi) * 128) + pgA;
                LDSM4(ah[mi][0], ah[mi][1], ah[mi][2], ah[mi][3], ro);
                LDSM4(al[mi][0], al[mi][1], al[mi][2], al[mi][3], ro + 16384);
            }
            uint32_t bh[2][4], bl[2][4];
            #pragma unroll
            for (int p = 0; p < 2; p++) {
                uint32_t ro = base + (uint32_t)((nbase + p * 16 + rowB) * 128) + pgB;
                LDSM4(bh[p][0], bh[p][1], bh[p][2], bh[p][3], ro + 32768);
                LDSM4(bl[p][0], bl[p][1], bl[p][2], bl[p][3], ro + 49152);
            }
            #pragma unroll
            for (int mi = 0; mi < 4; mi++)
                #pragma unroll
                for (int p = 0; p < 2; p++)
                    #pragma unroll
                    for (int s2 = 0; s2 < 2; s2++) {
                        float* cc = c[mi][p * 2 + s2];
                        MMA16816(cc, ah[mi], bh[p][2 * s2], bh[p][2 * s2 + 1]);
                        MMA16816(cc, ah[mi], bl[p][2 * s2], bl[p][2 * s2 + 1]);
                        MMA16816(cc, al[mi], bh[p][2 * s2], bh[p][2 * s2 + 1]);
                    }
        }
        __syncthreads();
    }
}

// ---------------- weight split + transpose ----------------
// layer1: W[128,256] -> combined [512][128]; layer2: W[256,256] -> [256][256]
__global__ void split_tr(const float* __restrict__ W1v, const float* __restrict__ W1p,
                         const float* __restrict__ W2v, const float* __restrict__ W2p)
{
    int idx = blockIdx.x * 256 + threadIdx.x;    // 0 .. 196607
    const float* W; __nv_bfloat16 *Hh, *Ll; int K, base, nofs;
    if (idx < 32768)       { W = W1v; Hh = g_w1_h;  Ll = g_w1_l;  K = 128; base = 0;      nofs = 0; }
    else if (idx < 65536)  { W = W1p; Hh = g_w1_h;  Ll = g_w1_l;  K = 128; base = 32768;  nofs = 256; }
    else if (idx < 131072) { W = W2v; Hh = g_w2v_h; Ll = g_w2v_l; K = 256; base = 65536;  nofs = 0; }
    else                   { W = W2p; Hh = g_w2p_h; Ll = g_w2p_l; K = 256; base = 131072; nofs = 0; }
    int j = idx - base;
    int k = j >> 8, n = (j & 255) + nofs;
    float x = W[j];
    __nv_bfloat16 h = __float2bfloat16(x);
    Hh[(size_t)n * K + k] = h;
    Ll[(size_t)n * K + k] = __float2bfloat16(x - __bfloat162float(h));
}

// ---------------- input split: s fp32 -> bf16 hi/lo ----------------
__global__ void split_input(const float* __restrict__ X,
                            __nv_bfloat16* __restrict__ Xh, __nv_bfloat16* __restrict__ Xl)
{
    int i = blockIdx.x * 256 + threadIdx.x;
    float4 v = ((const float4*)X)[i];
    __nv_bfloat162 h0, h1, l0, l1;
    h0.x = __float2bfloat16(v.x); l0.x = __float2bfloat16(v.x - __bfloat162float(h0.x));
    h0.y = __float2bfloat16(v.y); l0.y = __float2bfloat16(v.y - __bfloat162float(h0.y));
    h1.x = __float2bfloat16(v.z); l1.x = __float2bfloat16(v.z - __bfloat162float(h1.x));
    h1.y = __float2bfloat16(v.w); l1.y = __float2bfloat16(v.w - __bfloat162float(h1.y));
    ((__nv_bfloat162*)Xh)[2 * i]     = h0;
    ((__nv_bfloat162*)Xh)[2 * i + 1] = h1;
    ((__nv_bfloat162*)Xl)[2 * i]     = l0;
    ((__nv_bfloat162*)Xl)[2 * i + 1] = l1;
}

// bootstrap row: sp[T-1] -> row T of g_s buffers
__global__ void split_sp(const float* __restrict__ sp)
{
    int tid = threadIdx.x;   // 128 threads
    float x = sp[(size_t)(T - 1) * S + tid];
    __nv_bfloat16 h = __float2bfloat16(x);
    g_s_h[(size_t)T * S + tid] = h;
    g_s_l[(size_t)T * S + tid] = __float2bfloat16(x - __bfloat162float(h));
}

// ---------------- preset head accumulators ----------------
__global__ void presetK(const float* __restrict__ vhb, const float* __restrict__ mub)
{
    int t = blockIdx.x * 256 + threadIdx.x;
    if (t < TX) g_values[t] = vhb[0];
    if (t < T) {
        float4 m0 = *(const float4*)mub;
        float4 m1 = *(const float4*)(mub + 4);
        ((float4*)g_mu)[2 * t]     = m0;
        ((float4*)g_mu)[2 * t + 1] = m1;
    }
}

#define SMEM_SZ (131072 + 512 + 4096)

// ---------------- layer 1 fused (v+p), N=512, M=T+128 ----------------
__global__ void __launch_bounds__(256, 1) gemm_l1(
    const float* __restrict__ vb1, const float* __restrict__ pib1)
{
    extern __shared__ char smem[];
    const uint32_t s0 = smem_u32(smem);
    float* bias_s = (float*)(smem + 131072);

    const int tid = threadIdx.x;
    const int wid = tid >> 5, lane = tid & 31;
    const int n0 = blockIdx.x * 128;    // 0..383 over combined 512
    const int m0 = blockIdx.y * 128;
    const int mbase = (wid >> 2) * 64;
    const int nbase = (wid & 3) * 32;

    if (tid < 128) bias_s[tid] = (n0 < 256) ? vb1[n0 + tid] : pib1[n0 - 256 + tid];

    float c[4][4][4] = {};
    mma_tile((const uint4*)g_s_h + (size_t)m0 * 16, (const uint4*)g_s_l + (size_t)m0 * 16,
             (const uint4*)g_w1_h + (size_t)n0 * 16, (const uint4*)g_w1_l + (size_t)n0 * 16,
             16, 2, s0, c);

    __nv_bfloat16 *Yh, *Yl; int nb;
    if (n0 < 256) { Yh = g_h1v_h; Yl = g_h1v_l; nb = n0; }
    else          { Yh = g_h1p_h; Yl = g_h1p_l; nb = n0 - 256; }

    const int g = lane >> 2, tq = lane & 3;
    #pragma unroll
    for (int mi = 0; mi < 4; mi++) {
        int row = m0 + mbase + mi * 16 + g;
        #pragma unroll
        for (int ni = 0; ni < 4; ni++) {
            int colb = nbase + ni * 8 + 2 * tq;
            int col  = nb + colb;
            float b0 = bias_s[colb], b1 = bias_s[colb + 1];
            float v0 = tanhf(c[mi][ni][0] + b0);
            float v1 = tanhf(c[mi][ni][1] + b1);
            float v2 = tanhf(c[mi][ni][2] + b0);
            float v3 = tanhf(c[mi][ni][3] + b1);
            __nv_bfloat162 hA, lA, hB, lB;
            hA.x = __float2bfloat16(v0); lA.x = __float2bfloat16(v0 - __bfloat162float(hA.x));
            hA.y = __float2bfloat16(v1); lA.y = __float2bfloat16(v1 - __bfloat162float(hA.y));
            hB.x = __float2bfloat16(v2); lB.x = __float2bfloat16(v2 - __bfloat162float(hB.x));
            hB.y = __float2bfloat16(v3); lB.y = __float2bfloat16(v3 - __bfloat162float(hB.y));
            *(__nv_bfloat162*)(Yh + (size_t)row * 256 + col)       = hA;
            *(__nv_bfloat162*)(Yl + (size_t)row * 256 + col)       = lA;
            *(__nv_bfloat162*)(Yh + (size_t)(row + 8) * 256 + col) = hB;
            *(__nv_bfloat162*)(Yl + (size_t)(row + 8) * 256 + col) = lB;
        }
    }
}

// ---------------- layer 2 merged (z=0: v-net + value head, z=1: p-net + mu head) ----------------
__global__ void __launch_bounds__(256, 1) gemm_l2(
    const float* __restrict__ vb2, const float* __restrict__ pib2,
    const float* __restrict__ vhW, const float* __restrict__ muW)
{
    const int z = blockIdx.z;
    if (z == 1 && blockIdx.y == gridDim.y - 1) return;   // p-net: no bootstrap tile

    extern __shared__ char smem[];
    const uint32_t s0 = smem_u32(smem);
    float* bias_s = (float*)(smem + 131072);
    float* hW_s   = (float*)(smem + 131072 + 512);

    const int tid = threadIdx.x;
    const int wid = tid >> 5, lane = tid & 31;
    const int n0 = blockIdx.x * 128;
    const int m0 = blockIdx.y * 128;
    const int mbase = (wid >> 2) * 64;
    const int nbase = (wid & 3) * 32;

    const __nv_bfloat16 *Ah, *Al, *Bh, *Bl;
    if (z == 0) {
        Ah = g_h1v_h; Al = g_h1v_l; Bh = g_w2v_h; Bl = g_w2v_l;
        if (tid < 128) bias_s[tid] = vb2[n0 + tid];
        if (tid < 128) hW_s[tid]   = vhW[n0 + tid];
    } else {
        Ah = g_h1p_h; Al = g_h1p_l; Bh = g_w2p_h; Bl = g_w2p_l;
        if (tid < 128) bias_s[tid] = pib2[n0 + tid];
        for (int i = tid; i < 1024; i += 256) hW_s[i] = muW[n0 * 8 + i];
    }

    float c[4][4][4] = {};
    mma_tile((const uint4*)Ah + (size_t)m0 * 32, (const uint4*)Al + (size_t)m0 * 32,
             (const uint4*)Bh + (size_t)n0 * 32, (const uint4*)Bl + (size_t)n0 * 32,
             32, 4, s0, c);

    const int g = lane >> 2, tq = lane & 3;
    if (z == 0) {
        #pragma unroll
        for (int mi = 0; mi < 4; mi++) {
            float pv0 = 0.f, pv1 = 0.f;
            #pragma unroll
            for (int ni = 0; ni < 4; ni++) {
                int colb = nbase + ni * 8 + 2 * tq;
                float b0 = bias_s[colb], b1 = bias_s[colb + 1];
                float w0 = hW_s[colb],   w1 = hW_s[colb + 1];
                pv0 += tanhf(c[mi][ni][0] + b0) * w0 + tanhf(c[mi][ni][1] + b1) * w1;
                pv1 += tanhf(c[mi][ni][2] + b0) * w0 + tanhf(c[mi][ni][3] + b1) * w1;
            }
            pv0 += __shfl_xor_sync(0xffffffffu, pv0, 1);
            pv0 += __shfl_xor_sync(0xffffffffu, pv0, 2);
            pv1 += __shfl_xor_sync(0xffffffffu, pv1, 1);
            pv1 += __shfl_xor_sync(0xffffffffu, pv1, 2);
            if (tq == 0) {
                int row = m0 + mbase + mi * 16 + g;
                atomicAdd(&g_values[row],     pv0);
                atomicAdd(&g_values[row + 8], pv1);
            }
        }
    } else {
        #pragma unroll
        for (int mi = 0; mi < 4; mi++) {
            float pm0[8] = {}, pm1[8] = {};
            #pragma unroll
            for (int ni = 0; ni < 4; ni++) {
                int colb = nbase + ni * 8 + 2 * tq;
                float b0 = bias_s[colb], b1 = bias_s[colb + 1];
                float t0 = tanhf(c[mi][ni][0] + b0);
                float t1 = tanhf(c[mi][ni][1] + b1);
                float t2 = tanhf(c[mi][ni][2] + b0);
                float t3 = tanhf(c[mi][ni][3] + b1);
                #pragma unroll
                for (int j = 0; j < 8; j++) {
                    float w0 = hW_s[colb * 8 + j], w1 = hW_s[(colb + 1) * 8 + j];
                    pm0[j] += t0 * w0 + t1 * w1;
                    pm1[j] += t2 * w0 + t3 * w1;
                }
            }
            #pragma unroll
            for (int j = 0; j < 8; j++) {
                pm0[j] += __shfl_xor_sync(0xffffffffu, pm0[j], 1);
                pm0[j] += __shfl_xor_sync(0xffffffffu, pm0[j], 2);
                pm1[j] += __shfl_xor_sync(0xffffffffu, pm1[j], 1);
                pm1[j] += __shfl_xor_sync(0xffffffffu, pm1[j], 2);
            }
            if (tq == 0) {
                int row = m0 + mbase + mi * 16 + g;
                #pragma unroll
                for (int j = 0; j < 8; j++) {
                    atomicAdd(&g_mu[(size_t)row * 8 + j],       pm0[j]);
                    atomicAdd(&g_mu[(size_t)(row + 8) * 8 + j], pm1[j]);
                }
            }
        }
    }
}

// ---------------- GAE parallel scan (reversed-index linear recurrence) ----------------
__global__ __launch_bounds__(1024) void scan1(
    const float* __restrict__ r, const float* __restrict__ dmask)
{
    int u = blockIdx.x * 1024 + threadIdx.x;
    int t = T - 1 - u;
    float m  = dmask[t];
    float nv = g_values[t + 1];                          // [T] = bootstrap
    float bb = r[t] + GAMMA_C * nv * m - g_values[t];    // delta
    float aa = GL * m;

    int lane = threadIdx.x & 31, warp = threadIdx.x >> 5;
    #pragma unroll
    for (int off = 1; off < 32; off <<= 1) {
        float ap = __shfl_up_sync(0xffffffffu, aa, off);
        float bp = __shfl_up_sync(0xffffffffu, bb, off);
        if (lane >= off) { bb = fmaf(aa, bp, bb); aa *= ap; }
    }
    __shared__ float wA[32], wB[32];
    if (lane == 31) { wA[warp] = aa; wB[warp] = bb; }
    __syncthreads();
    if (warp == 0) {
        float a2 = wA[lane], b2 = wB[lane];
        #pragma unroll
        for (int off = 1; off < 32; off <<= 1) {
            float ap = __shfl_up_sync(0xffffffffu, a2, off);
            float bp = __shfl_up_sync(0xffffffffu, b2, off);
            if (lane >= off) { b2 = fmaf(a2, bp, b2); a2 *= ap; }
        }
        wA[lane] = a2; wB[lane] = b2;
    }
    __syncthreads();
    if (warp > 0) {
        float pa = wA[warp - 1], pb = wB[warp - 1];
        bb = fmaf(aa, pb, bb);
        aa *= pa;
    }
    g_Aloc[u] = aa;
    g_Bloc[u] = bb;
    if (threadIdx.x == 1023) { g_Ablk[blockIdx.x] = aa; g_Bblk[blockIdx.x] = bb; }
}

__global__ void scan2()
{
    if (threadIdx.x == 0) {
        float g = 0.f;
        for (int j = 0; j < 64; j++) {
            g_Gin[j] = g;
            g = fmaf(g_Ablk[j], g, g_Bblk[j]);
        }
    }
    if (threadIdx.x < 4) g_stats[threadIdx.x] = 0.f;   // zero accumulators (per graph replay)
}

__global__ __launch_bounds__(1024) void scan3()
{
    int u = blockIdx.x * 1024 + threadIdx.x;
    float g = fmaf(g_Aloc[u], g_Gin[blockIdx.x], g_Bloc[u]);
    g_adv[T - 1 - u] = g;

    float s1 = g, s2 = g * g;
    #pragma unroll
    for (int o = 16; o; o >>= 1) {
        s1 += __shfl_down_sync(0xffffffffu, s1, o);
        s2 += __shfl_down_sync(0xffffffffu, s2, o);
    }
    __shared__ float rA[32], rB[32];
    int lane = threadIdx.x & 31, warp = threadIdx.x >> 5;
    if (lane == 0) { rA[warp] = s1; rB[warp] = s2; }
    __syncthreads();
    if (warp == 0) {
        float t1 = rA[lane], t2 = rB[lane];
        #pragma unroll
        for (int o = 16; o; o >>= 1) {
            t1 += __shfl_down_sync(0xffffffffu, t1, o);
            t2 += __shfl_down_sync(0xffffffffu, t2, o);
        }
        if (lane == 0) {
            atomicAdd(&g_stats[0], t1);
            atomicAdd(&g_stats[1], t2);
        }
    }
}

// ---------------- PPO loss terms (ratio computed inline from g_mu) ----------------
__global__ __launch_bounds__(256) void loss_kernel(
    const float* __restrict__ a, const float* __restrict__ lpo,
    const float* __restrict__ logstd)
{
    int t = blockIdx.x * 256 + threadIdx.x;
    float mean = g_stats[0] * (1.f / (float)T);
    float var  = (g_stats[1] - (float)T * mean * mean) * (1.f / (float)(T - 1));
    float sd   = sqrtf(fmaxf(var, 0.f));

    float lp = 0.f;
    #pragma unroll
    for (int j = 0; j < A; j++) {
        float mu = g_mu[(size_t)t * 8 + j];
        float ls = logstd[j];
        float d  = (a[(size_t)t * 8 + j] - mu) * expf(-ls);
        lp += -0.5f * d * d - ls;
    }
    lp -= 0.5f * LOG2PI * (float)A;
    float rt = expf(lp - lpo[t]);

    float adv  = g_adv[t];
    float advn = (adv - mean) / (sd + 1e-8f);
    float clip = fminf(fmaxf(rt, 1.f - EPSC), 1.f + EPSC);
    float pg   = -fminf(rt * advn, clip * advn);
    float ax   = fabsf(adv);
    float vf   = (ax < 1.f) ? 0.5f * adv * adv : ax - 0.5f;

    #pragma unroll
    for (int o = 16; o; o >>= 1) {
        pg += __shfl_down_sync(0xffffffffu, pg, o);
        vf += __shfl_down_sync(0xffffffffu, vf, o);
    }
    __shared__ float rA[8], rB[8];
    int lane = threadIdx.x & 31, warp = threadIdx.x >> 5;
    if (lane == 0) { rA[warp] = pg; rB[warp] = vf; }
    __syncthreads();
    if (warp == 0 && lane < 8) {
        float t1 = rA[lane], t2 = rB[lane];
        #pragma unroll
        for (int o = 4; o; o >>= 1) {
            t1 += __shfl_down_sync(0xffu, t1, o);
            t2 += __shfl_down_sync(0xffu, t2, o);
        }
        if (lane == 0) {
            atomicAdd(&g_stats[2], t1);
            atomicAdd(&g_stats[3], t2);
        }
    }
}

__global__ void finalize_kernel(const float* __restrict__ logstd, float* __restrict__ out)
{
    if (threadIdx.x == 0) {
        float ent = 0.f;
        #pragma unroll
        for (int j = 0; j < A; j++) ent += 0.5f + 0.5f * LOG2PI + logstd[j];
        ent *= (1.f / (float)A);
        out[0] = g_stats[2] * (1.f / (float)T)
               + 0.5f * g_stats[3] * (1.f / (float)T)
               - 0.01f * ent;
    }
}

// ---------------- launch ----------------
extern "C" void kernel_launch(void* const* d_in, const int* in_sizes, int n_in,
                              void* d_out, int out_size)
{
    const float* s_in  = (const float*)d_in[0];
    const float* a_in  = (const float*)d_in[1];
    const float* r_in  = (const float*)d_in[2];
    const float* sp_in = (const float*)d_in[3];
    const float* lpo   = (const float*)d_in[4];
    const float* dmask = (const float*)d_in[5];
    const float* piW1  = (const float*)d_in[6];
    const float* pib1  = (const float*)d_in[7];
    const float* piW2  = (const float*)d_in[8];
    const float* pib2  = (const float*)d_in[9];
    const float* muW   = (const float*)d_in[10];
    const float* mub   = (const float*)d_in[11];
    const float* lstd  = (const float*)d_in[12];
    const float* vW1   = (const float*)d_in[13];
    const float* vb1   = (const float*)d_in[14];
    const float* vW2   = (const float*)d_in[15];
    const float* vb2   = (const float*)d_in[16];
    const float* vhW   = (const float*)d_in[17];
    const float* vhb   = (const float*)d_in[18];
    float* out = (float*)d_out;

    __nv_bfloat16* s_h;
    __nv_bfloat16* s_l;
    { void* p; cudaGetSymbolAddress(&p, g_s_h); s_h = (__nv_bfloat16*)p; }
    { void* p; cudaGetSymbolAddress(&p, g_s_l); s_l = (__nv_bfloat16*)p; }

    cudaFuncSetAttribute(gemm_l1, cudaFuncAttributeMaxDynamicSharedMemorySize, SMEM_SZ);
    cudaFuncSetAttribute(gemm_l2, cudaFuncAttributeMaxDynamicSharedMemorySize, SMEM_SZ);

    // prep (tiny)
    split_tr<<<768, 256>>>(vW1, piW1, vW2, piW2);
    split_input<<<(T * S / 4) / 256, 256>>>(s_in, s_h, s_l);
    split_sp<<<1, 128>>>(sp_in);
    presetK<<<(TX + 255) / 256, 256>>>(vhb, mub);

    // layer 1: fused v+p, N=512, M includes bootstrap tile
    gemm_l1<<<dim3(4, T / 128 + 1), 256, SMEM_SZ>>>(vb1, pib1);
    // layer 2: merged v/p with fused heads (h2 never touches DRAM)
    gemm_l2<<<dim3(2, T / 128 + 1, 2), 256, SMEM_SZ>>>(vb2, pib2, vhW, muW);

    scan1<<<64, 1024>>>(r_in, dmask);
    scan2<<<1, 32>>>();
    scan3<<<64, 1024>>>();

    loss_kernel<<<T / 256, 256>>>(a_in, lpo, lstd);
    finalize_kernel<<<1, 32>>>(lstd, out);
}

// round 7
// speedup vs baseline: 3.3354x; 1.4256x over previous
#include <cuda_runtime.h>
#include <cuda_fp16.h>
#include <math.h>
#include <stdint.h>

// ---------------- constants ----------------
constexpr int   T       = 65536;
constexpr int   S       = 128;
constexpr int   H       = 256;
constexpr int   A       = 8;
constexpr float GAMMA_C = 0.99f;
constexpr float GL      = 0.99f * 0.95f;     // gamma * lambda
constexpr float EPSC    = 0.2f;
constexpr float LOG2PI  = 1.8378770664093453f;
constexpr int   TX      = T + 128;           // T plus bootstrap tile

// ---------------- device scratch (static: no allocations allowed) ----------------
__device__ __align__(16) __half g_s_h[(size_t)TX * S];
__device__ __align__(16) __half g_s_l[(size_t)TX * S];
__device__ __align__(16) __half g_h1v_h[(size_t)TX * H], g_h1v_l[(size_t)TX * H];
__device__ __align__(16) __half g_h1p_h[(size_t)TX * H], g_h1p_l[(size_t)TX * H];
__device__ float g_values[TX];               // [T] = bootstrap value v(sp[-1])
__device__ __align__(16) float g_mu[(size_t)T * A];
__device__ float g_Aloc[T];
__device__ float g_Bloc[T];
__device__ float g_adv[T];
__device__ float g_Ablk[64];
__device__ float g_Bblk[64];
__device__ float g_Gin[64];
__device__ float g_stats[4];   // [0]=sum adv, [1]=sum adv^2, [2]=sum pg, [3]=sum vf

// transposed weights (single fp16): layer1 combined [512][128]; layer2 [256][256] each
__device__ __align__(16) __half g_w1[65536];
__device__ __align__(16) __half g_w2v[65536];
__device__ __align__(16) __half g_w2p[65536];

// ---------------- PTX helpers ----------------
__device__ __forceinline__ uint32_t smem_u32(const void* p) {
    return (uint32_t)__cvta_generic_to_shared(p);
}

__device__ __forceinline__ void cpasync16(uint32_t dst, const void* src) {
    asm volatile("cp.async.cg.shared.global [%0], [%1], 16;" :: "r"(dst), "l"(src));
}

#define CP_COMMIT()  asm volatile("cp.async.commit_group;")
#define CP_WAIT0()   asm volatile("cp.async.wait_group 0;" ::: "memory")
#define CP_WAIT1()   asm volatile("cp.async.wait_group 1;" ::: "memory")

#define LDSM4(r0, r1, r2, r3, addr)                                                 \
    asm volatile("ldmatrix.sync.aligned.m8n8.x4.shared.b16 {%0,%1,%2,%3}, [%4];"    \
        : "=r"(r0), "=r"(r1), "=r"(r2), "=r"(r3) : "r"(addr))

#define MMAF16(cc, a, b0, b1)                                                       \
    asm volatile("mma.sync.aligned.m16n8k16.row.col.f32.f16.f16.f32 "               \
        "{%0,%1,%2,%3}, {%4,%5,%6,%7}, {%8,%9}, {%0,%1,%2,%3};"                     \
        : "+f"((cc)[0]), "+f"((cc)[1]), "+f"((cc)[2]), "+f"((cc)[3])                \
        : "r"((a)[0]), "r"((a)[1]), "r"((a)[2]), "r"((a)[3]), "r"(b0), "r"(b1))

// ---------------- shared GEMM mainloop (2-stage cp.async pipeline, k-chunk 64) ----------------
// A split fp16 hi/lo, B single fp16. Stage: Ah@0, Al@16K, B@32K (48KB); stages at 0/49152.
__device__ __forceinline__ void mma_tile(
    const uint4* __restrict__ Ahi, const uint4* __restrict__ Alo,
    const uint4* __restrict__ Bp,
    int KG, int nc, uint32_t s0, float c[4][4][4])
{
    const int tid = threadIdx.x;
    const int wid = tid >> 5, lane = tid & 31;
    const int mbase = (wid >> 2) * 64;
    const int nbase = (wid & 3) * 32;
    const int l7    = lane & 7;
    const int rowA  = mbase + (lane & 15);
    const int halfA = lane >> 4;
    const int rowB  = (lane & 7) + ((lane >> 4) & 1) * 8;
    const int halfB = (lane >> 3) & 1;

    auto load_chunk = [&](int st, int ch) {
        uint32_t base = s0 + (uint32_t)st * 49152u;
        int kg0 = ch * 8;
        #pragma unroll
        for (int i = 0; i < 4; i++) {
            int idx = i * 256 + tid;
            int row = idx >> 3, g = idx & 7;
            uint32_t d = base + (uint32_t)(row * 128 + ((g ^ (row & 7)) << 4));
            size_t sx = (size_t)row * KG + kg0 + g;
            cpasync16(d,          Ahi + sx);
            cpasync16(d + 16384,  Alo + sx);
            cpasync16(d + 32768,  Bp  + sx);
        }
    };

    load_chunk(0, 0); CP_COMMIT();

    for (int ch = 0; ch < nc; ch++) {
        if (ch + 1 < nc) { load_chunk((ch + 1) & 1, ch + 1); CP_COMMIT(); CP_WAIT1(); }
        else             { CP_WAIT0(); }
        __syncthreads();

        uint32_t base = s0 + (uint32_t)(ch & 1) * 49152u;
        #pragma unroll
        for (int ks = 0; ks < 4; ks++) {
            int kgA = 2 * ks + halfA;
            uint32_t pgA = (uint32_t)((kgA ^ l7) << 4);
            int kgB = 2 * ks + halfB;
            uint32_t pgB = (uint32_t)((kgB ^ l7) << 4);

            uint32_t ah[4][4], al[4][4];
            #pragma unroll
            for (int mi = 0; mi < 4; mi++) {
                uint32_t ro = base + (uint32_t)((rowA + 16 * mi) * 128) + pgA;
                LDSM4(ah[mi][0], ah[mi][1], ah[mi][2], ah[mi][3], ro);
                LDSM4(al[mi][0], al[mi][1], al[mi][2], al[mi][3], ro + 16384);
            }
            uint32_t b[2][4];
            #pragma unroll
            for (int p = 0; p < 2; p++) {
                uint32_t ro = base + (uint32_t)((nbase + p * 16 + rowB) * 128) + pgB;
                LDSM4(b[p][0], b[p][1], b[p][2], b[p][3], ro + 32768);
            }
            #pragma unroll
            for (int mi = 0; mi < 4; mi++)
                #pragma unroll
                for (int p = 0; p < 2; p++)
                    #pragma unroll
                    for (int s2 = 0; s2 < 2; s2++) {
                        float* cc = c[mi][p * 2 + s2];
                        MMAF16(cc, ah[mi], b[p][2 * s2], b[p][2 * s2 + 1]);
                        MMAF16(cc, al[mi], b[p][2 * s2], b[p][2 * s2 + 1]);
                    }
        }
        __syncthreads();
    }
}

// ---------------- prep: weight transpose->fp16, presets, bootstrap row ----------------
__global__ void prep_misc(const float* __restrict__ W1v, const float* __restrict__ W1p,
                          const float* __restrict__ W2v, const float* __restrict__ W2p,
                          const float* __restrict__ sp,
                          const float* __restrict__ vhb, const float* __restrict__ mub)
{
    int idx = blockIdx.x * 256 + threadIdx.x;    // 0 .. 196607
    {
        const float* W; __half* Wt; int K, base, nofs;
        if (idx < 32768)       { W = W1v; Wt = g_w1;  K = 128; base = 0;      nofs = 0; }
        else if (idx < 65536)  { W = W1p; Wt = g_w1;  K = 128; base = 32768;  nofs = 256; }
        else if (idx < 131072) { W = W2v; Wt = g_w2v; K = 256; base = 65536;  nofs = 0; }
        else                   { W = W2p; Wt = g_w2p; K = 256; base = 131072; nofs = 0; }
        int j = idx - base;
        int k = j >> 8, n = (j & 255) + nofs;
        Wt[(size_t)n * K + k] = __float2half_rn(W[j]);
    }
    if (idx < TX) g_values[idx] = vhb[0];
    if (idx < T) {
        float4 m0 = *(const float4*)mub;
        float4 m1 = *(const float4*)(mub + 4);
        ((float4*)g_mu)[2 * idx]     = m0;
        ((float4*)g_mu)[2 * idx + 1] = m1;
    }
    if (idx < 128) {
        float x = sp[(size_t)(T - 1) * S + idx];
        __half h = __float2half_rn(x);
        g_s_h[(size_t)T * S + idx] = h;
        g_s_l[(size_t)T * S + idx] = __float2half_rn(x - __half2float(h));
    }
}

// ---------------- input split: s fp32 -> fp16 hi/lo ----------------
__global__ void split_input(const float* __restrict__ X,
                            __half* __restrict__ Xh, __half* __restrict__ Xl)
{
    int i = blockIdx.x * 256 + threadIdx.x;
    float4 v = ((const float4*)X)[i];
    __half2 h0, h1, l0, l1;
    h0.x = __float2half_rn(v.x); l0.x = __float2half_rn(v.x - __half2float(h0.x));
    h0.y = __float2half_rn(v.y); l0.y = __float2half_rn(v.y - __half2float(h0.y));
    h1.x = __float2half_rn(v.z); l1.x = __float2half_rn(v.z - __half2float(h1.x));
    h1.y = __float2half_rn(v.w); l1.y = __float2half_rn(v.w - __half2float(h1.y));
    ((__half2*)Xh)[2 * i]     = h0;
    ((__half2*)Xh)[2 * i + 1] = h1;
    ((__half2*)Xl)[2 * i]     = l0;
    ((__half2*)Xl)[2 * i + 1] = l1;
}

#define SMEM_SZ (98304 + 512 + 4096)

// ---------------- layer 1 fused (v+p), N=512, M=T+128 ----------------
__global__ void __launch_bounds__(256, 2) gemm_l1(
    const float* __restrict__ vb1, const float* __restrict__ pib1)
{
    extern __shared__ char smem[];
    const uint32_t s0 = smem_u32(smem);
    float* bias_s = (float*)(smem + 98304);

    const int tid = threadIdx.x;
    const int wid = tid >> 5, lane = tid & 31;
    const int n0 = blockIdx.x * 128;    // 0..383 over combined 512
    const int m0 = blockIdx.y * 128;
    const int mbase = (wid >> 2) * 64;
    const int nbase = (wid & 3) * 32;

    if (tid < 128) bias_s[tid] = (n0 < 256) ? vb1[n0 + tid] : pib1[n0 - 256 + tid];

    float c[4][4][4] = {};
    mma_tile((const uint4*)g_s_h + (size_t)m0 * 16, (const uint4*)g_s_l + (size_t)m0 * 16,
             (const uint4*)g_w1 + (size_t)n0 * 16, 16, 2, s0, c);

    __half *Yh, *Yl; int nb;
    if (n0 < 256) { Yh = g_h1v_h; Yl = g_h1v_l; nb = n0; }
    else          { Yh = g_h1p_h; Yl = g_h1p_l; nb = n0 - 256; }

    const int g = lane >> 2, tq = lane & 3;
    #pragma unroll
    for (int mi = 0; mi < 4; mi++) {
        int row = m0 + mbase + mi * 16 + g;
        #pragma unroll
        for (int ni = 0; ni < 4; ni++) {
            int colb = nbase + ni * 8 + 2 * tq;
            int col  = nb + colb;
            float b0 = bias_s[colb], b1 = bias_s[colb + 1];
            float v0 = tanhf(c[mi][ni][0] + b0);
            float v1 = tanhf(c[mi][ni][1] + b1);
            float v2 = tanhf(c[mi][ni][2] + b0);
            float v3 = tanhf(c[mi][ni][3] + b1);
            __half2 hA, lA, hB, lB;
            hA.x = __float2half_rn(v0); lA.x = __float2half_rn(v0 - __half2float(hA.x));
            hA.y = __float2half_rn(v1); lA.y = __float2half_rn(v1 - __half2float(hA.y));
            hB.x = __float2half_rn(v2); lB.x = __float2half_rn(v2 - __half2float(hB.x));
            hB.y = __float2half_rn(v3); lB.y = __float2half_rn(v3 - __half2float(hB.y));
            *(__half2*)(Yh + (size_t)row * 256 + col)       = hA;
            *(__half2*)(Yl + (size_t)row * 256 + col)       = lA;
            *(__half2*)(Yh + (size_t)(row + 8) * 256 + col) = hB;
            *(__half2*)(Yl + (size_t)(row + 8) * 256 + col) = lB;
        }
    }
}

// ---------------- layer 2 merged (z=0: v-net + value head, z=1: p-net + mu head) ----------------
__global__ void __launch_bounds__(256, 2) gemm_l2(
    const float* __restrict__ vb2, const float* __restrict__ pib2,
    const float* __restrict__ vhW, const float* __restrict__ muW)
{
    const int z = blockIdx.z;
    if (z == 1 && blockIdx.y == gridDim.y - 1) return;   // p-net: no bootstrap tile

    extern __shared__ char smem[];
    const uint32_t s0 = smem_u32(smem);
    float* bias_s = (float*)(smem + 98304);
    float* hW_s   = (float*)(smem + 98304 + 512);

    const int tid = threadIdx.x;
    const int wid = tid >> 5, lane = tid & 31;
    const int n0 = blockIdx.x * 128;
    const int m0 = blockIdx.y * 128;
    const int mbase = (wid >> 2) * 64;
    const int nbase = (wid & 3) * 32;

    const __half *Ah, *Al, *Bp;
    if (z == 0) {
        Ah = g_h1v_h; Al = g_h1v_l; Bp = g_w2v;
        if (tid < 128) bias_s[tid] = vb2[n0 + tid];
        if (tid < 128) hW_s[tid]   = vhW[n0 + tid];
    } else {
        Ah = g_h1p_h; Al = g_h1p_l; Bp = g_w2p;
        if (tid < 128) bias_s[tid] = pib2[n0 + tid];
        for (int i = tid; i < 1024; i += 256) hW_s[i] = muW[n0 * 8 + i];
    }

    float c[4][4][4] = {};
    mma_tile((const uint4*)Ah + (size_t)m0 * 32, (const uint4*)Al + (size_t)m0 * 32,
             (const uint4*)Bp + (size_t)n0 * 32, 32, 4, s0, c);

    const int g = lane >> 2, tq = lane & 3;
    if (z == 0) {
        #pragma unroll
        for (int mi = 0; mi < 4; mi++) {
            float pv0 = 0.f, pv1 = 0.f;
            #pragma unroll
            for (int ni = 0; ni < 4; ni++) {
                int colb = nbase + ni * 8 + 2 * tq;
                float b0 = bias_s[colb], b1 = bias_s[colb + 1];
                float w0 = hW_s[colb],   w1 = hW_s[colb + 1];
                pv0 += tanhf(c[mi][ni][0] + b0) * w0 + tanhf(c[mi][ni][1] + b1) * w1;
                pv1 += tanhf(c[mi][ni][2] + b0) * w0 + tanhf(c[mi][ni][3] + b1) * w1;
            }
            pv0 += __shfl_xor_sync(0xffffffffu, pv0, 1);
            pv0 += __shfl_xor_sync(0xffffffffu, pv0, 2);
            pv1 += __shfl_xor_sync(0xffffffffu, pv1, 1);
            pv1 += __shfl_xor_sync(0xffffffffu, pv1, 2);
            if (tq == 0) {
                int row = m0 + mbase + mi * 16 + g;
                atomicAdd(&g_values[row],     pv0);
                atomicAdd(&g_values[row + 8], pv1);
            }
        }
    } else {
        #pragma unroll
        for (int mi = 0; mi < 4; mi++) {
            float pm0[8] = {}, pm1[8] = {};
            #pragma unroll
            for (int ni = 0; ni < 4; ni++) {
                int colb = nbase + ni * 8 + 2 * tq;
                float b0 = bias_s[colb], b1 = bias_s[colb + 1];
                float t0 = tanhf(c[mi][ni][0] + b0);
                float t1 = tanhf(c[mi][ni][1] + b1);
                float t2 = tanhf(c[mi][ni][2] + b0);
                float t3 = tanhf(c[mi][ni][3] + b1);
                #pragma unroll
                for (int j = 0; j < 8; j++) {
                    float w0 = hW_s[colb * 8 + j], w1 = hW_s[(colb + 1) * 8 + j];
                    pm0[j] += t0 * w0 + t1 * w1;
                    pm1[j] += t2 * w0 + t3 * w1;
                }
            }
            #pragma unroll
            for (int j = 0; j < 8; j++) {
                pm0[j] += __shfl_xor_sync(0xffffffffu, pm0[j], 1);
                pm0[j] += __shfl_xor_sync(0xffffffffu, pm0[j], 2);
                pm1[j] += __shfl_xor_sync(0xffffffffu, pm1[j], 1);
                pm1[j] += __shfl_xor_sync(0xffffffffu, pm1[j], 2);
            }
            if (tq == 0) {
                int row = m0 + mbase + mi * 16 + g;
                #pragma unroll
                for (int j = 0; j < 8; j++) {
                    atomicAdd(&g_mu[(size_t)row * 8 + j],       pm0[j]);
                    atomicAdd(&g_mu[(size_t)(row + 8) * 8 + j], pm1[j]);
                }
            }
        }
    }
}

// ---------------- GAE parallel scan (reversed-index linear recurrence) ----------------
__global__ __launch_bounds__(1024) void scan1(
    const float* __restrict__ r, const float* __restrict__ dmask)
{
    int u = blockIdx.x * 1024 + threadIdx.x;
    int t = T - 1 - u;
    float m  = dmask[t];
    float nv = g_values[t + 1];                          // [T] = bootstrap
    float bb = r[t] + GAMMA_C * nv * m - g_values[t];    // delta
    float aa = GL * m;

    int lane = threadIdx.x & 31, warp = threadIdx.x >> 5;
    #pragma unroll
    for (int off = 1; off < 32; off <<= 1) {
        float ap = __shfl_up_sync(0xffffffffu, aa, off);
        float bp = __shfl_up_sync(0xffffffffu, bb, off);
        if (lane >= off) { bb = fmaf(aa, bp, bb); aa *= ap; }
    }
    __shared__ float wA[32], wB[32];
    if (lane == 31) { wA[warp] = aa; wB[warp] = bb; }
    __syncthreads();
    if (warp == 0) {
        float a2 = wA[lane], b2 = wB[lane];
        #pragma unroll
        for (int off = 1; off < 32; off <<= 1) {
            float ap = __shfl_up_sync(0xffffffffu, a2, off);
            float bp = __shfl_up_sync(0xffffffffu, b2, off);
            if (lane >= off) { b2 = fmaf(a2, bp, b2); a2 *= ap; }
        }
        wA[lane] = a2; wB[lane] = b2;
    }
    __syncthreads();
    if (warp > 0) {
        float pa = wA[warp - 1], pb = wB[warp - 1];
        bb = fmaf(aa, pb, bb);
        aa *= pa;
    }
    g_Aloc[u] = aa;
    g_Bloc[u] = bb;
    if (threadIdx.x == 1023) { g_Ablk[blockIdx.x] = aa; g_Bblk[blockIdx.x] = bb; }
}

__global__ void scan2()
{
    if (threadIdx.x == 0) {
        float g = 0.f;
        for (int j = 0; j < 64; j++) {
            g_Gin[j] = g;
            g = fmaf(g_Ablk[j], g, g_Bblk[j]);
        }
    }
    if (threadIdx.x < 4) g_stats[threadIdx.x] = 0.f;   // zero accumulators (per graph replay)
}

__global__ __launch_bounds__(1024) void scan3()
{
    int u = blockIdx.x * 1024 + threadIdx.x;
    float g = fmaf(g_Aloc[u], g_Gin[blockIdx.x], g_Bloc[u]);
    g_adv[T - 1 - u] = g;

    float s1 = g, s2 = g * g;
    #pragma unroll
    for (int o = 16; o; o >>= 1) {
        s1 += __shfl_down_sync(0xffffffffu, s1, o);
        s2 += __shfl_down_sync(0xffffffffu, s2, o);
    }
    __shared__ float rA[32], rB[32];
    int lane = threadIdx.x & 31, warp = threadIdx.x >> 5;
    if (lane == 0) { rA[warp] = s1; rB[warp] = s2; }
    __syncthreads();
    if (warp == 0) {
        float t1 = rA[lane], t2 = rB[lane];
        #pragma unroll
        for (int o = 16; o; o >>= 1) {
            t1 += __shfl_down_sync(0xffffffffu, t1, o);
            t2 += __shfl_down_sync(0xffffffffu, t2, o);
        }
        if (lane == 0) {
            atomicAdd(&g_stats[0], t1);
            atomicAdd(&g_stats[1], t2);
        }
    }
}

// ---------------- PPO loss terms (ratio computed inline from g_mu) ----------------
__global__ __launch_bounds__(256) void loss_kernel(
    const float* __restrict__ a, const float* __restrict__ lpo,
    const float* __restrict__ logstd)
{
    int t = blockIdx.x * 256 + threadIdx.x;
    float mean = g_stats[0] * (1.f / (float)T);
    float var  = (g_stats[1] - (float)T * mean * mean) * (1.f / (float)(T - 1));
    float sd   = sqrtf(fmaxf(var, 0.f));

    float lp = 0.f;
    #pragma unroll
    for (int j = 0; j < A; j++) {
        float mu = g_mu[(size_t)t * 8 + j];
        float ls = logstd[j];
        float d  = (a[(size_t)t * 8 + j] - mu) * expf(-ls);
        lp += -0.5f * d * d - ls;
    }
    lp -= 0.5f * LOG2PI * (float)A;
    float rt = expf(lp - lpo[t]);

    float adv  = g_adv[t];
    float advn = (adv - mean) / (sd + 1e-8f);
    float clip = fminf(fmaxf(rt, 1.f - EPSC), 1.f + EPSC);
    float pg   = -fminf(rt * advn, clip * advn);
    float ax   = fabsf(adv);
    float vf   = (ax < 1.f) ? 0.5f * adv * adv : ax - 0.5f;

    #pragma unroll
    for (int o = 16; o; o >>= 1) {
        pg += __shfl_down_sync(0xffffffffu, pg, o);
        vf += __shfl_down_sync(0xffffffffu, vf, o);
    }
    __shared__ float rA[8], rB[8];
    int lane = threadIdx.x & 31, warp = threadIdx.x >> 5;
    if (lane == 0) { rA[warp] = pg; rB[warp] = vf; }
    __syncthreads();
    if (warp == 0 && lane < 8) {
        float t1 = rA[lane], t2 = rB[lane];
        #pragma unroll
        for (int o = 4; o; o >>= 1) {
            t1 += __shfl_down_sync(0xffu, t1, o);
            t2 += __shfl_down_sync(0xffu, t2, o);
        }
        if (lane == 0) {
            atomicAdd(&g_stats[2], t1);
            atomicAdd(&g_stats[3], t2);
        }
    }
}

__global__ void finalize_kernel(const float* __restrict__ logstd, float* __restrict__ out)
{
    if (threadIdx.x == 0) {
        float ent = 0.f;
        #pragma unroll
        for (int j = 0; j < A; j++) ent += 0.5f + 0.5f * LOG2PI + logstd[j];
        ent *= (1.f / (float)A);
        out[0] = g_stats[2] * (1.f / (float)T)
               + 0.5f * g_stats[3] * (1.f / (float)T)
               - 0.01f * ent;
    }
}

// ---------------- launch ----------------
extern "C" void kernel_launch(void* const* d_in, const int* in_sizes, int n_in,
                              void* d_out, int out_size)
{
    const float* s_in  = (const float*)d_in[0];
    const float* a_in  = (const float*)d_in[1];
    const float* r_in  = (const float*)d_in[2];
    const float* sp_in = (const float*)d_in[3];
    const float* lpo   = (const float*)d_in[4];
    const float* dmask = (const float*)d_in[5];
    const float* piW1  = (const float*)d_in[6];
    const float* pib1  = (const float*)d_in[7];
    const float* piW2  = (const float*)d_in[8];
    const float* pib2  = (const float*)d_in[9];
    const float* muW   = (const float*)d_in[10];
    const float* mub   = (const float*)d_in[11];
    const float* lstd  = (const float*)d_in[12];
    const float* vW1   = (const float*)d_in[13];
    const float* vb1   = (const float*)d_in[14];
    const float* vW2   = (const float*)d_in[15];
    const float* vb2   = (const float*)d_in[16];
    const float* vhW   = (const float*)d_in[17];
    const float* vhb   = (const float*)d_in[18];
    float* out = (float*)d_out;

    __half* s_h;
    __half* s_l;
    { void* p; cudaGetSymbolAddress(&p, g_s_h); s_h = (__half*)p; }
    { void* p; cudaGetSymbolAddress(&p, g_s_l); s_l = (__half*)p; }

    cudaFuncSetAttribute(gemm_l1, cudaFuncAttributeMaxDynamicSharedMemorySize, SMEM_SZ);
    cudaFuncSetAttribute(gemm_l2, cudaFuncAttributeMaxDynamicSharedMemorySize, SMEM_SZ);

    // prep (tiny)
    prep_misc<<<768, 256>>>(vW1, piW1, vW2, piW2, sp_in, vhb, mub);
    split_input<<<(T * S / 4) / 256, 256>>>(s_in, s_h, s_l);

    // layer 1: fused v+p, N=512, M includes bootstrap tile
    gemm_l1<<<dim3(4, T / 128 + 1), 256, SMEM_SZ>>>(vb1, pib1);
    // layer 2: merged v/p with fused heads (h2 never touches DRAM)
    gemm_l2<<<dim3(2, T / 128 + 1, 2), 256, SMEM_SZ>>>(vb2, pib2, vhW, muW);

    scan1<<<64, 1024>>>(r_in, dmask);
    scan2<<<1, 32>>>();
    scan3<<<64, 1024>>>();

    loss_kernel<<<T / 256, 256>>>(a_in, lpo, lstd);
    finalize_kernel<<<1, 32>>>(lstd, out);
}